// round 6
// baseline (speedup 1.0000x reference)
#include <cuda_runtime.h>
#include <cstdint>
#include <math.h>

typedef unsigned long long u64;

#define NB   4096
#define NL   50
#define NT   64
#define NF   3
#define NH   20
#define NG   80
#define NO   16
#define NSEQ (NB*NL)        // 204800
#define TPB  64
#define NPAIR (NSEQ/2)      // 102400
#define NCTA_L (NPAIR/TPB)  // 1600

// ---------------- device scratch (static; zero-initialized at load) -------------
__device__ int   g_hist[64];
__device__ int   g_off[64];
__device__ int   g_order[NSEQ];
__device__ float g_hout[(size_t)NSEQ * NH];

// ---------------- packed f32x2 helpers ------------------------------------------
__device__ __forceinline__ u64 f2pack(float lo, float hi) {
    u64 r; asm("mov.b64 %0, {%1, %2};" : "=l"(r) : "f"(lo), "f"(hi)); return r;
}
__device__ __forceinline__ void f2unpack(u64 v, float& lo, float& hi) {
    asm("mov.b64 {%0, %1}, %2;" : "=f"(lo), "=f"(hi) : "l"(v));
}
__device__ __forceinline__ u64 ffma2(u64 a, u64 b, u64 c) {
    u64 d; asm("fma.rn.f32x2 %0, %1, %2, %3;" : "=l"(d) : "l"(a), "l"(b), "l"(c)); return d;
}

// accurate activations: MUFU.EX2 + MUFU.RCP (~1e-6 rel err)
__device__ __forceinline__ float fsig(float v) {
    return __fdividef(1.0f, 1.0f + __expf(-v));
}
__device__ __forceinline__ float ftanh(float v) {
    return __fdividef(2.0f, 1.0f + __expf(-2.0f * v)) - 1.0f;
}

// ---------------- counting sort, descending length, 3 launches -------------------
__global__ void k_hist(const int* __restrict__ lengths) {
    __shared__ int sh[64];
    if (threadIdx.x < 64) sh[threadIdx.x] = 0;
    __syncthreads();
    int i = blockIdx.x * 256 + threadIdx.x;
    if (i < NSEQ) atomicAdd(&sh[lengths[i] & 63], 1);
    __syncthreads();
    if (threadIdx.x < 64 && sh[threadIdx.x]) atomicAdd(&g_hist[threadIdx.x], sh[threadIdx.x]);
}
// exclusive offsets (descending buckets) + RESET g_hist (deterministic on replay)
__global__ void k_scan() {
    if (threadIdx.x == 0) {
        int acc = 0;
        #pragma unroll
        for (int i = 63; i >= 0; --i) { int v = g_hist[i]; g_off[i] = acc; acc += v; }
    }
    __syncthreads();
    if (threadIdx.x < 64) g_hist[threadIdx.x] = 0;
}
__global__ void k_scatter(const int* __restrict__ lengths) {
    __shared__ int sh[64], base[64];
    if (threadIdx.x < 64) sh[threadIdx.x] = 0;
    __syncthreads();
    int i = blockIdx.x * 256 + threadIdx.x, l = 0, r = 0;
    if (i < NSEQ) { l = lengths[i] & 63; r = atomicAdd(&sh[l], 1); }
    __syncthreads();
    if (threadIdx.x < 64) {
        int c = sh[threadIdx.x];
        if (c) base[threadIdx.x] = atomicAdd(&g_off[threadIdx.x], c);
    }
    __syncthreads();
    if (i < NSEQ) g_order[base[l] + r] = i;
}

// ---------------- LSTM: 2 seqs/thread, rolled j (unroll 2), h in named regs ------
// shared (static, 35840 B total -> 6 CTAs/SM = 12 warps/SM):
//   sWhh2[(j*4+g)*20+k] = w_hh[(g*20+j)*20+k] as (w,w) pairs   12800 B
//   sC[j*16+e]: e<4 bias(i,f,g,o); e>=4 w_ih gate-major          2560 B
//   cbuf / hnbuf [20*64]                                      2x10240 B

#define ACCG(acc, wbase) do {                                                  \
    const ulonglong2* wp_ = (const ulonglong2*)(wbase);                        \
    ulonglong2 w_;                                                             \
    w_ = wp_[0]; acc = ffma2(h0,  w_.x, acc); acc = ffma2(h1,  w_.y, acc);     \
    w_ = wp_[1]; acc = ffma2(h2,  w_.x, acc); acc = ffma2(h3,  w_.y, acc);     \
    w_ = wp_[2]; acc = ffma2(h4,  w_.x, acc); acc = ffma2(h5,  w_.y, acc);     \
    w_ = wp_[3]; acc = ffma2(h6,  w_.x, acc); acc = ffma2(h7,  w_.y, acc);     \
    w_ = wp_[4]; acc = ffma2(h8,  w_.x, acc); acc = ffma2(h9,  w_.y, acc);     \
    w_ = wp_[5]; acc = ffma2(h10, w_.x, acc); acc = ffma2(h11, w_.y, acc);     \
    w_ = wp_[6]; acc = ffma2(h12, w_.x, acc); acc = ffma2(h13, w_.y, acc);     \
    w_ = wp_[7]; acc = ffma2(h14, w_.x, acc); acc = ffma2(h15, w_.y, acc);     \
    w_ = wp_[8]; acc = ffma2(h16, w_.x, acc); acc = ffma2(h17, w_.y, acc);     \
    w_ = wp_[9]; acc = ffma2(h18, w_.x, acc); acc = ffma2(h19, w_.y, acc);     \
} while (0)

#define SNAP(dst, SEL) do { float lo_, hi_;                                    \
    f2unpack(h0,  lo_, hi_); (dst)[0]  = SEL;                                  \
    f2unpack(h1,  lo_, hi_); (dst)[1]  = SEL;                                  \
    f2unpack(h2,  lo_, hi_); (dst)[2]  = SEL;                                  \
    f2unpack(h3,  lo_, hi_); (dst)[3]  = SEL;                                  \
    f2unpack(h4,  lo_, hi_); (dst)[4]  = SEL;                                  \
    f2unpack(h5,  lo_, hi_); (dst)[5]  = SEL;                                  \
    f2unpack(h6,  lo_, hi_); (dst)[6]  = SEL;                                  \
    f2unpack(h7,  lo_, hi_); (dst)[7]  = SEL;                                  \
    f2unpack(h8,  lo_, hi_); (dst)[8]  = SEL;                                  \
    f2unpack(h9,  lo_, hi_); (dst)[9]  = SEL;                                  \
    f2unpack(h10, lo_, hi_); (dst)[10] = SEL;                                  \
    f2unpack(h11, lo_, hi_); (dst)[11] = SEL;                                  \
    f2unpack(h12, lo_, hi_); (dst)[12] = SEL;                                  \
    f2unpack(h13, lo_, hi_); (dst)[13] = SEL;                                  \
    f2unpack(h14, lo_, hi_); (dst)[14] = SEL;                                  \
    f2unpack(h15, lo_, hi_); (dst)[15] = SEL;                                  \
    f2unpack(h16, lo_, hi_); (dst)[16] = SEL;                                  \
    f2unpack(h17, lo_, hi_); (dst)[17] = SEL;                                  \
    f2unpack(h18, lo_, hi_); (dst)[18] = SEL;                                  \
    f2unpack(h19, lo_, hi_); (dst)[19] = SEL;                                  \
} while (0)

__global__ void __launch_bounds__(TPB)
k_lstm(const float* __restrict__ x, const int* __restrict__ lengths,
       const float* __restrict__ w_ih, const float* __restrict__ w_hh,
       const float* __restrict__ b_ih, const float* __restrict__ b_hh)
{
    __shared__ __align__(16) u64 sWhh2[NH * 4 * NH];   // 12800 B
    __shared__ __align__(16) u64 sC[NH * 16];          //  2560 B
    __shared__ __align__(16) u64 cbuf[NH * TPB];       // 10240 B
    __shared__ __align__(16) u64 hnbuf[NH * TPB];      // 10240 B

    const int tid = threadIdx.x;

    // stage + reorder weights: 4 gate rows contiguous per hidden j
    for (int i = tid; i < NH * 4 * NH; i += TPB) {
        int j = i / 80, g = (i / 20) & 3, k = i % 20;
        float w = w_hh[(g * 20 + j) * 20 + k];
        sWhh2[i] = f2pack(w, w);
    }
    for (int i = tid; i < NH * 16; i += TPB) {
        int j = i >> 4, e = i & 15;
        float w;
        if (e < 4) { int r = e * 20 + j; w = b_ih[r] + b_hh[r]; }
        else { int g = (e - 4) / 3, k = (e - 4) % 3; w = w_ih[(g * 20 + j) * 3 + k]; }
        sC[i] = f2pack(w, w);
    }
    #pragma unroll
    for (int j = 0; j < NH; ++j) cbuf[j * TPB + tid] = 0ull;
    __syncthreads();

    const int pid = blockIdx.x * TPB + tid;
    const int s0 = g_order[2 * pid];
    const int s1 = g_order[2 * pid + 1];
    const int len0 = lengths[s0];
    const int len1 = lengths[s1];
    const int tmax = max(len0, len1);

    const float* p0 = x + (size_t)s0 * (NT * NF);
    const float* p1 = x + (size_t)s1 * (NT * NF);

    // h state: 20 NAMED u64 regs
    u64 h0 = 0, h1 = 0, h2 = 0, h3 = 0, h4 = 0, h5 = 0, h6 = 0, h7 = 0, h8 = 0,
        h9 = 0, h10 = 0, h11 = 0, h12 = 0, h13 = 0, h14 = 0, h15 = 0, h16 = 0,
        h17 = 0, h18 = 0, h19 = 0;

    u64 x0 = 0, x1 = 0, x2 = 0;
    if (tmax > 0) {
        x0 = f2pack(p0[0], p1[0]);
        x1 = f2pack(p0[1], p1[1]);
        x2 = f2pack(p0[2], p1[2]);
    }

    for (int t = 0; t < tmax; ++t) {
        const int tn = min(t + 1, NT - 1);
        const u64 nx0 = f2pack(p0[3 * tn + 0], p1[3 * tn + 0]);
        const u64 nx1 = f2pack(p0[3 * tn + 1], p1[3 * tn + 1]);
        const u64 nx2 = f2pack(p0[3 * tn + 2], p1[3 * tn + 2]);

        #pragma unroll 2
        for (int j = 0; j < NH; ++j) {
            // merged per-j constants: bias(i,f,g,o) + 12 w_ih pairs, 8x LDS.128
            const ulonglong2* cb_ = (const ulonglong2*)(sC + j * 16);
            const ulonglong2 b01 = cb_[0], b23 = cb_[1];
            const ulonglong2 wa = cb_[2], wb = cb_[3], wc = cb_[4];
            const ulonglong2 wd = cb_[5], we = cb_[6], wf = cb_[7];

            u64 ai = b01.x, af = b01.y, ag = b23.x, ao = b23.y;
            ai = ffma2(x0, wa.x, ai); ai = ffma2(x1, wa.y, ai); ai = ffma2(x2, wb.x, ai);
            af = ffma2(x0, wb.y, af); af = ffma2(x1, wc.x, af); af = ffma2(x2, wc.y, af);
            ag = ffma2(x0, wd.x, ag); ag = ffma2(x1, wd.y, ag); ag = ffma2(x2, we.x, ag);
            ao = ffma2(x0, we.y, ao); ao = ffma2(x1, wf.x, ao); ao = ffma2(x2, wf.y, ao);

            ACCG(ai, sWhh2 + j * 80);
            ACCG(af, sWhh2 + j * 80 + 20);
            ACCG(ag, sWhh2 + j * 80 + 40);
            ACCG(ao, sWhh2 + j * 80 + 60);

            float ia, ib, fa, fb, ga, gb, oa, ob, ca, cb2;
            f2unpack(ai, ia, ib); f2unpack(af, fa, fb);
            f2unpack(ag, ga, gb); f2unpack(ao, oa, ob);
            f2unpack(cbuf[j * TPB + tid], ca, cb2);

            float cn0 = fsig(fa) * ca  + fsig(ia) * ftanh(ga);
            float cn1 = fsig(fb) * cb2 + fsig(ib) * ftanh(gb);
            float hn0 = fsig(oa) * ftanh(cn0);
            float hn1 = fsig(ob) * ftanh(cn1);

            cbuf[j * TPB + tid]  = f2pack(cn0, cn1);
            hnbuf[j * TPB + tid] = f2pack(hn0, hn1);
        }

        // commit h from staging into named regs
        #define RELOAD(k) h##k = hnbuf[(k) * TPB + tid];
        RELOAD(0)  RELOAD(1)  RELOAD(2)  RELOAD(3)  RELOAD(4)
        RELOAD(5)  RELOAD(6)  RELOAD(7)  RELOAD(8)  RELOAD(9)
        RELOAD(10) RELOAD(11) RELOAD(12) RELOAD(13) RELOAD(14)
        RELOAD(15) RELOAD(16) RELOAD(17) RELOAD(18) RELOAD(19)
        #undef RELOAD

        // snapshot final h when a sequence completes
        const int tp1 = t + 1;
        if (tp1 == len0) { float* d = g_hout + (size_t)s0 * NH; SNAP(d, lo_); }
        if (tp1 == len1) { float* d = g_hout + (size_t)s1 * NH; SNAP(d, hi_); }

        x0 = nx0; x1 = nx1; x2 = nx2;
    }
}

// ---------------- conv + FC kernel (incl. layer summary) -------------------------
#define C1OUT 46
#define C2OUT 22
#define C3OUT 19

__global__ void __launch_bounds__(128)
k_conv(const int* __restrict__ lengths,
       const float* __restrict__ w_lin, const float* __restrict__ b_lin,
       const float* __restrict__ c1_w, const float* __restrict__ c1_b,
       const float* __restrict__ c2_w, const float* __restrict__ c2_b,
       const float* __restrict__ c3_w, const float* __restrict__ c3_b,
       const float* __restrict__ fc1_w, const float* __restrict__ fc1_b,
       const float* __restrict__ fc2_w, const float* __restrict__ fc2_b,
       float* __restrict__ out)
{
    __shared__ float sbuf[10272];
    __shared__ float sh[NL * NH];
    __shared__ float swl[NO * NH];
    __shared__ float sbl[NO];
    __shared__ int   slen[NL];
    __shared__ float sfc[16];

    float* feat = sbuf;
    float* w1   = sbuf + 800;
    float* y1   = sbuf + 3360;
    float* w2   = sbuf + 4832;
    float* y2   = sbuf + 8928;
    float* y3   = sbuf + 9632;
    float* w3   = sbuf;   // reuse after conv2

    const int b   = blockIdx.x;
    const int tid = threadIdx.x;

    if (tid < NL) slen[tid] = lengths[b * NL + tid];
    for (int i = tid; i < NO * NH; i += 128) swl[i] = w_lin[i];
    if (tid < NO) sbl[tid] = b_lin[tid];
    __syncthreads();
    for (int i = tid; i < NL * NH; i += 128) {
        int l = i / NH, k = i % NH;
        sh[i] = (slen[l] > 0) ? g_hout[(size_t)(b * NL + l) * NH + k] : 0.0f;
    }
    for (int i = tid; i < 2560; i += 128) w1[i] = c1_w[i];
    for (int i = tid; i < 4096; i += 128) w2[i] = c2_w[i];
    __syncthreads();

    for (int i = tid; i < NO * NL; i += 128) {
        int c = i / NL, l = i % NL;
        float s = sbl[c];
        #pragma unroll
        for (int k = 0; k < NH; ++k) s += sh[l * NH + k] * swl[c * NH + k];
        feat[c * NL + l] = (slen[l] > 0) ? fsig(s) : 0.0f;
    }
    __syncthreads();

    for (int idx = tid; idx < 32 * C1OUT; idx += 128) {
        int o = idx / C1OUT, ppos = idx % C1OUT;
        float acc = c1_b[o];
        #pragma unroll
        for (int c = 0; c < 16; ++c) {
            const float* f = feat + c * 50 + ppos;
            const float* w = w1 + (o * 16 + c) * 5;
            #pragma unroll
            for (int k = 0; k < 5; ++k) acc += f[k] * w[k];
        }
        y1[o * C1OUT + ppos] = fmaxf(acc, 0.0f);
    }
    __syncthreads();

    for (int idx = tid; idx < 32 * C2OUT; idx += 128) {
        int o = idx / C2OUT, ppos = idx % C2OUT;
        float acc = c2_b[o];
        #pragma unroll
        for (int c = 0; c < 32; ++c) {
            const float* f = y1 + c * C1OUT + 2 * ppos;
            const float* w = w2 + (o * 32 + c) * 4;
            #pragma unroll
            for (int k = 0; k < 4; ++k) acc += f[k] * w[k];
        }
        y2[o * C2OUT + ppos] = fmaxf(acc, 0.0f);
    }
    __syncthreads();

    for (int i = tid; i < 4096; i += 128) w3[i] = c3_w[i];
    __syncthreads();

    for (int idx = tid; idx < 32 * C3OUT; idx += 128) {
        int o = idx / C3OUT, ppos = idx % C3OUT;
        float acc = c3_b[o];
        #pragma unroll
        for (int c = 0; c < 32; ++c) {
            const float* f = y2 + c * C2OUT + ppos;
            const float* w = w3 + (o * 32 + c) * 4;
            #pragma unroll
            for (int k = 0; k < 4; ++k) acc += f[k] * w[k];
        }
        y3[o * C3OUT + ppos] = fmaxf(acc, 0.0f);
    }
    __syncthreads();

    {
        const int wd = tid >> 5, lane = tid & 31;
        for (int o = wd; o < 16; o += 4) {
            float a = 0.0f;
            const float* w = fc1_w + o * 608;
            for (int k = lane; k < 608; k += 32) a += y3[k] * w[k];
            #pragma unroll
            for (int s = 16; s > 0; s >>= 1) a += __shfl_xor_sync(0xffffffffu, a, s);
            if (lane == 0) sfc[o] = fmaxf(a + fc1_b[o], 0.0f);
        }
    }
    __syncthreads();

    if (tid < 4) {
        float a = fc2_b[tid];
        #pragma unroll
        for (int k = 0; k < 16; ++k) a += sfc[k] * fc2_w[tid * 16 + k];
        out[(size_t)b * 4 + tid] = a;
    }
}

// ---------------- launch ----------------------------------------------------------
extern "C" void kernel_launch(void* const* d_in, const int* in_sizes, int n_in,
                              void* d_out, int out_size)
{
    const float* x       = (const float*)d_in[0];
    const int*   lengths = (const int*)  d_in[1];
    const float* w_ih    = (const float*)d_in[2];
    const float* w_hh    = (const float*)d_in[3];
    const float* b_ih    = (const float*)d_in[4];
    const float* b_hh    = (const float*)d_in[5];
    const float* w_lin   = (const float*)d_in[6];
    const float* b_lin   = (const float*)d_in[7];
    const float* c1_w    = (const float*)d_in[8];
    const float* c1_b    = (const float*)d_in[9];
    const float* c2_w    = (const float*)d_in[10];
    const float* c2_b    = (const float*)d_in[11];
    const float* c3_w    = (const float*)d_in[12];
    const float* c3_b    = (const float*)d_in[13];
    const float* fc1_w   = (const float*)d_in[14];
    const float* fc1_b   = (const float*)d_in[15];
    const float* fc2_w   = (const float*)d_in[16];
    const float* fc2_b   = (const float*)d_in[17];
    float* out = (float*)d_out;

    // counting sort by length, descending (g_hist reset inside k_scan)
    k_hist<<<(NSEQ + 255) / 256, 256>>>(lengths);
    k_scan<<<1, 64>>>();
    k_scatter<<<(NSEQ + 255) / 256, 256>>>(lengths);

    // LSTM: 2 seqs/thread, rolled j-loop (unroll 2), snapshot-at-length
    k_lstm<<<NCTA_L, TPB>>>(x, lengths, w_ih, w_hh, b_ih, b_hh);

    // layer summary + conv stack + classifier head
    k_conv<<<NB, 128>>>(lengths, w_lin, b_lin, c1_w, c1_b, c2_w, c2_b, c3_w, c3_b,
                        fc1_w, fc1_b, fc2_w, fc2_b, out);
}

// round 7
// speedup vs baseline: 1.1592x; 1.1592x over previous
#include <cuda_runtime.h>
#include <cstdint>
#include <math.h>

typedef unsigned long long u64;

#define NB   4096
#define NL   50
#define NT   64
#define NF   3
#define NH   20
#define NG   80
#define NO   16
#define NSEQ (NB*NL)        // 204800
#define TPB  64
#define NQUAD (NSEQ/4)      // 51200
#define NCTA_L (NQUAD/TPB)  // 800

// ---------------- device scratch (static; zero-initialized at load) -------------
__device__ int   g_hist[64];
__device__ int   g_off[64];
__device__ int   g_order[NSEQ];
__device__ float g_hout[(size_t)NSEQ * NH];

// ---------------- packed f32x2 helpers ------------------------------------------
__device__ __forceinline__ u64 f2pack(float lo, float hi) {
    u64 r; asm("mov.b64 %0, {%1, %2};" : "=l"(r) : "f"(lo), "f"(hi)); return r;
}
__device__ __forceinline__ void f2unpack(u64 v, float& lo, float& hi) {
    asm("mov.b64 {%0, %1}, %2;" : "=f"(lo), "=f"(hi) : "l"(v));
}
__device__ __forceinline__ u64 ffma2(u64 a, u64 b, u64 c) {
    u64 d; asm("fma.rn.f32x2 %0, %1, %2, %3;" : "=l"(d) : "l"(a), "l"(b), "l"(c)); return d;
}

// accurate activations: MUFU.EX2 + MUFU.RCP (~1e-6 rel err)
__device__ __forceinline__ float fsig(float v) {
    return __fdividef(1.0f, 1.0f + __expf(-v));
}
__device__ __forceinline__ float ftanh(float v) {
    return __fdividef(2.0f, 1.0f + __expf(-2.0f * v)) - 1.0f;
}

// ---------------- counting sort, descending length, 3 launches -------------------
__global__ void k_hist(const int* __restrict__ lengths) {
    __shared__ int sh[64];
    if (threadIdx.x < 64) sh[threadIdx.x] = 0;
    __syncthreads();
    int i = blockIdx.x * 256 + threadIdx.x;
    if (i < NSEQ) atomicAdd(&sh[lengths[i] & 63], 1);
    __syncthreads();
    if (threadIdx.x < 64 && sh[threadIdx.x]) atomicAdd(&g_hist[threadIdx.x], sh[threadIdx.x]);
}
__global__ void k_scan() {
    if (threadIdx.x == 0) {
        int acc = 0;
        #pragma unroll
        for (int i = 63; i >= 0; --i) { int v = g_hist[i]; g_off[i] = acc; acc += v; }
    }
    __syncthreads();
    if (threadIdx.x < 64) g_hist[threadIdx.x] = 0;   // deterministic on graph replay
}
__global__ void k_scatter(const int* __restrict__ lengths) {
    __shared__ int sh[64], base[64];
    if (threadIdx.x < 64) sh[threadIdx.x] = 0;
    __syncthreads();
    int i = blockIdx.x * 256 + threadIdx.x, l = 0, r = 0;
    if (i < NSEQ) { l = lengths[i] & 63; r = atomicAdd(&sh[l], 1); }
    __syncthreads();
    if (threadIdx.x < 64) {
        int c = sh[threadIdx.x];
        if (c) base[threadIdx.x] = atomicAdd(&g_off[threadIdx.x], c);
    }
    __syncthreads();
    if (i < NSEQ) g_order[base[l] + r] = i;
}

// ---------------- LSTM: 4 seqs/thread (2 packs), unroll 2, 16B state slots -------
// shared (static, 56320 B -> 4 CTAs/SM):
//   sWhh2[(j*4+g)*20+k] as (w,w) pairs                         12800 B
//   sC[j*16+e]: e<4 bias(i,f,g,o); e>=4 w_ih gate-major          2560 B
//   cbuf/hnbuf: ulonglong2[20*64] (both packs in one 16B slot) 2x20480 B

// one weight load -> 4 ffma2 (both packs)
#define ACC2(accA, accB, wbase) do {                                           \
    const ulonglong2* wp_ = (const ulonglong2*)(wbase);                        \
    ulonglong2 w_;                                                             \
    w_ = wp_[0];                                                               \
    accA = ffma2(hA0,  w_.x, accA); accB = ffma2(hB0,  w_.x, accB);            \
    accA = ffma2(hA1,  w_.y, accA); accB = ffma2(hB1,  w_.y, accB);            \
    w_ = wp_[1];                                                               \
    accA = ffma2(hA2,  w_.x, accA); accB = ffma2(hB2,  w_.x, accB);            \
    accA = ffma2(hA3,  w_.y, accA); accB = ffma2(hB3,  w_.y, accB);            \
    w_ = wp_[2];                                                               \
    accA = ffma2(hA4,  w_.x, accA); accB = ffma2(hB4,  w_.x, accB);            \
    accA = ffma2(hA5,  w_.y, accA); accB = ffma2(hB5,  w_.y, accB);            \
    w_ = wp_[3];                                                               \
    accA = ffma2(hA6,  w_.x, accA); accB = ffma2(hB6,  w_.x, accB);            \
    accA = ffma2(hA7,  w_.y, accA); accB = ffma2(hB7,  w_.y, accB);            \
    w_ = wp_[4];                                                               \
    accA = ffma2(hA8,  w_.x, accA); accB = ffma2(hB8,  w_.x, accB);            \
    accA = ffma2(hA9,  w_.y, accA); accB = ffma2(hB9,  w_.y, accB);            \
    w_ = wp_[5];                                                               \
    accA = ffma2(hA10, w_.x, accA); accB = ffma2(hB10, w_.x, accB);            \
    accA = ffma2(hA11, w_.y, accA); accB = ffma2(hB11, w_.y, accB);            \
    w_ = wp_[6];                                                               \
    accA = ffma2(hA12, w_.x, accA); accB = ffma2(hB12, w_.x, accB);            \
    accA = ffma2(hA13, w_.y, accA); accB = ffma2(hB13, w_.y, accB);            \
    w_ = wp_[7];                                                               \
    accA = ffma2(hA14, w_.x, accA); accB = ffma2(hB14, w_.x, accB);            \
    accA = ffma2(hA15, w_.y, accA); accB = ffma2(hB15, w_.y, accB);            \
    w_ = wp_[8];                                                               \
    accA = ffma2(hA16, w_.x, accA); accB = ffma2(hB16, w_.x, accB);            \
    accA = ffma2(hA17, w_.y, accA); accB = ffma2(hB17, w_.y, accB);            \
    w_ = wp_[9];                                                               \
    accA = ffma2(hA18, w_.x, accA); accB = ffma2(hB18, w_.x, accB);            \
    accA = ffma2(hA19, w_.y, accA); accB = ffma2(hB19, w_.y, accB);            \
} while (0)

// snapshot one lane of one pack (P in {hA,hB}, SEL in {lo_,hi_})
#define SNAP(P, SEL, dst) do { float lo_, hi_;                                 \
    f2unpack(P##0,  lo_, hi_); (dst)[0]  = SEL;                                \
    f2unpack(P##1,  lo_, hi_); (dst)[1]  = SEL;                                \
    f2unpack(P##2,  lo_, hi_); (dst)[2]  = SEL;                                \
    f2unpack(P##3,  lo_, hi_); (dst)[3]  = SEL;                                \
    f2unpack(P##4,  lo_, hi_); (dst)[4]  = SEL;                                \
    f2unpack(P##5,  lo_, hi_); (dst)[5]  = SEL;                                \
    f2unpack(P##6,  lo_, hi_); (dst)[6]  = SEL;                                \
    f2unpack(P##7,  lo_, hi_); (dst)[7]  = SEL;                                \
    f2unpack(P##8,  lo_, hi_); (dst)[8]  = SEL;                                \
    f2unpack(P##9,  lo_, hi_); (dst)[9]  = SEL;                                \
    f2unpack(P##10, lo_, hi_); (dst)[10] = SEL;                                \
    f2unpack(P##11, lo_, hi_); (dst)[11] = SEL;                                \
    f2unpack(P##12, lo_, hi_); (dst)[12] = SEL;                                \
    f2unpack(P##13, lo_, hi_); (dst)[13] = SEL;                                \
    f2unpack(P##14, lo_, hi_); (dst)[14] = SEL;                                \
    f2unpack(P##15, lo_, hi_); (dst)[15] = SEL;                                \
    f2unpack(P##16, lo_, hi_); (dst)[16] = SEL;                                \
    f2unpack(P##17, lo_, hi_); (dst)[17] = SEL;                                \
    f2unpack(P##18, lo_, hi_); (dst)[18] = SEL;                                \
    f2unpack(P##19, lo_, hi_); (dst)[19] = SEL;                                \
} while (0)

__global__ void __launch_bounds__(TPB)
k_lstm(const float* __restrict__ x, const int* __restrict__ lengths,
       const float* __restrict__ w_ih, const float* __restrict__ w_hh,
       const float* __restrict__ b_ih, const float* __restrict__ b_hh)
{
    __shared__ __align__(16) u64 sWhh2[NH * 4 * NH];       // 12800 B
    __shared__ __align__(16) u64 sC[NH * 16];              //  2560 B
    __shared__ __align__(16) ulonglong2 cbuf[NH * TPB];    // 20480 B
    __shared__ __align__(16) ulonglong2 hnbuf[NH * TPB];   // 20480 B

    const int tid = threadIdx.x;

    for (int i = tid; i < NH * 4 * NH; i += TPB) {
        int j = i / 80, g = (i / 20) & 3, k = i % 20;
        float w = w_hh[(g * 20 + j) * 20 + k];
        sWhh2[i] = f2pack(w, w);
    }
    for (int i = tid; i < NH * 16; i += TPB) {
        int j = i >> 4, e = i & 15;
        float w;
        if (e < 4) { int r = e * 20 + j; w = b_ih[r] + b_hh[r]; }
        else { int g = (e - 4) / 3, k = (e - 4) % 3; w = w_ih[(g * 20 + j) * 3 + k]; }
        sC[i] = f2pack(w, w);
    }
    #pragma unroll
    for (int j = 0; j < NH; ++j) cbuf[j * TPB + tid] = make_ulonglong2(0ull, 0ull);
    __syncthreads();

    const int qid = blockIdx.x * TPB + tid;
    const int s0 = g_order[4 * qid + 0];
    const int s1 = g_order[4 * qid + 1];
    const int s2 = g_order[4 * qid + 2];
    const int s3 = g_order[4 * qid + 3];
    const int len0 = lengths[s0], len1 = lengths[s1];
    const int len2 = lengths[s2], len3 = lengths[s3];
    const int tmax = max(max(len0, len1), max(len2, len3));

    const float* p0 = x + (size_t)s0 * (NT * NF);
    const float* p1 = x + (size_t)s1 * (NT * NF);
    const float* p2 = x + (size_t)s2 * (NT * NF);
    const float* p3 = x + (size_t)s3 * (NT * NF);

    // h state: 40 named u64 (hn staged in shared -> bounded live set)
    u64 hA0 = 0, hA1 = 0, hA2 = 0, hA3 = 0, hA4 = 0, hA5 = 0, hA6 = 0, hA7 = 0,
        hA8 = 0, hA9 = 0, hA10 = 0, hA11 = 0, hA12 = 0, hA13 = 0, hA14 = 0,
        hA15 = 0, hA16 = 0, hA17 = 0, hA18 = 0, hA19 = 0;
    u64 hB0 = 0, hB1 = 0, hB2 = 0, hB3 = 0, hB4 = 0, hB5 = 0, hB6 = 0, hB7 = 0,
        hB8 = 0, hB9 = 0, hB10 = 0, hB11 = 0, hB12 = 0, hB13 = 0, hB14 = 0,
        hB15 = 0, hB16 = 0, hB17 = 0, hB18 = 0, hB19 = 0;

    u64 xA0 = 0, xA1 = 0, xA2 = 0, xB0 = 0, xB1 = 0, xB2 = 0;
    if (tmax > 0) {
        xA0 = f2pack(p0[0], p1[0]); xA1 = f2pack(p0[1], p1[1]); xA2 = f2pack(p0[2], p1[2]);
        xB0 = f2pack(p2[0], p3[0]); xB1 = f2pack(p2[1], p3[1]); xB2 = f2pack(p2[2], p3[2]);
    }

    for (int t = 0; t < tmax; ++t) {
        const int tn = min(t + 1, NT - 1);
        const u64 nA0 = f2pack(p0[3 * tn + 0], p1[3 * tn + 0]);
        const u64 nA1 = f2pack(p0[3 * tn + 1], p1[3 * tn + 1]);
        const u64 nA2 = f2pack(p0[3 * tn + 2], p1[3 * tn + 2]);
        const u64 nB0 = f2pack(p2[3 * tn + 0], p3[3 * tn + 0]);
        const u64 nB1 = f2pack(p2[3 * tn + 1], p3[3 * tn + 1]);
        const u64 nB2 = f2pack(p2[3 * tn + 2], p3[3 * tn + 2]);

        #pragma unroll 2
        for (int j = 0; j < NH; ++j) {
            const ulonglong2* cb_ = (const ulonglong2*)(sC + j * 16);
            const ulonglong2 b01 = cb_[0], b23 = cb_[1];
            const ulonglong2 wa = cb_[2], wb = cb_[3], wc = cb_[4];
            const ulonglong2 wd = cb_[5], we = cb_[6], wf = cb_[7];

            u64 aiA = b01.x, afA = b01.y, agA = b23.x, aoA = b23.y;
            u64 aiB = b01.x, afB = b01.y, agB = b23.x, aoB = b23.y;

            aiA = ffma2(xA0, wa.x, aiA); aiB = ffma2(xB0, wa.x, aiB);
            aiA = ffma2(xA1, wa.y, aiA); aiB = ffma2(xB1, wa.y, aiB);
            aiA = ffma2(xA2, wb.x, aiA); aiB = ffma2(xB2, wb.x, aiB);
            afA = ffma2(xA0, wb.y, afA); afB = ffma2(xB0, wb.y, afB);
            afA = ffma2(xA1, wc.x, afA); afB = ffma2(xB1, wc.x, afB);
            afA = ffma2(xA2, wc.y, afA); afB = ffma2(xB2, wc.y, afB);
            agA = ffma2(xA0, wd.x, agA); agB = ffma2(xB0, wd.x, agB);
            agA = ffma2(xA1, wd.y, agA); agB = ffma2(xB1, wd.y, agB);
            agA = ffma2(xA2, we.x, agA); agB = ffma2(xB2, we.x, agB);
            aoA = ffma2(xA0, we.y, aoA); aoB = ffma2(xB0, we.y, aoB);
            aoA = ffma2(xA1, wf.x, aoA); aoB = ffma2(xB1, wf.x, aoB);
            aoA = ffma2(xA2, wf.y, aoA); aoB = ffma2(xB2, wf.y, aoB);

            ACC2(aiA, aiB, sWhh2 + j * 80);
            ACC2(afA, afB, sWhh2 + j * 80 + 20);
            ACC2(agA, agB, sWhh2 + j * 80 + 40);
            ACC2(aoA, aoB, sWhh2 + j * 80 + 60);

            const ulonglong2 cold = cbuf[j * TPB + tid];
            float ia, ib, fa, fb, ga, gb, oa, ob, c0, c1, h0, h1;
            ulonglong2 cnew, hnew;

            f2unpack(aiA, ia, ib); f2unpack(afA, fa, fb);
            f2unpack(agA, ga, gb); f2unpack(aoA, oa, ob);
            f2unpack(cold.x, c0, c1);
            c0 = fsig(fa) * c0 + fsig(ia) * ftanh(ga);
            c1 = fsig(fb) * c1 + fsig(ib) * ftanh(gb);
            h0 = fsig(oa) * ftanh(c0);
            h1 = fsig(ob) * ftanh(c1);
            cnew.x = f2pack(c0, c1);
            hnew.x = f2pack(h0, h1);

            f2unpack(aiB, ia, ib); f2unpack(afB, fa, fb);
            f2unpack(agB, ga, gb); f2unpack(aoB, oa, ob);
            f2unpack(cold.y, c0, c1);
            c0 = fsig(fa) * c0 + fsig(ia) * ftanh(ga);
            c1 = fsig(fb) * c1 + fsig(ib) * ftanh(gb);
            h0 = fsig(oa) * ftanh(c0);
            h1 = fsig(ob) * ftanh(c1);
            cnew.y = f2pack(c0, c1);
            hnew.y = f2pack(h0, h1);

            cbuf[j * TPB + tid]  = cnew;
            hnbuf[j * TPB + tid] = hnew;
        }

        // commit h from staging into named regs
        #define RELOAD(k) { ulonglong2 v_ = hnbuf[(k) * TPB + tid]; hA##k = v_.x; hB##k = v_.y; }
        RELOAD(0)  RELOAD(1)  RELOAD(2)  RELOAD(3)  RELOAD(4)
        RELOAD(5)  RELOAD(6)  RELOAD(7)  RELOAD(8)  RELOAD(9)
        RELOAD(10) RELOAD(11) RELOAD(12) RELOAD(13) RELOAD(14)
        RELOAD(15) RELOAD(16) RELOAD(17) RELOAD(18) RELOAD(19)
        #undef RELOAD

        const int tp1 = t + 1;
        if (tp1 == len0) { float* d = g_hout + (size_t)s0 * NH; SNAP(hA, lo_, d); }
        if (tp1 == len1) { float* d = g_hout + (size_t)s1 * NH; SNAP(hA, hi_, d); }
        if (tp1 == len2) { float* d = g_hout + (size_t)s2 * NH; SNAP(hB, lo_, d); }
        if (tp1 == len3) { float* d = g_hout + (size_t)s3 * NH; SNAP(hB, hi_, d); }

        xA0 = nA0; xA1 = nA1; xA2 = nA2;
        xB0 = nB0; xB1 = nB1; xB2 = nB2;
    }
}

// ---------------- conv + FC kernel: weight-reuse restructure ---------------------
#define C1OUT 46
#define C2OUT 22
#define C3OUT 19

__global__ void __launch_bounds__(128)
k_conv(const int* __restrict__ lengths,
       const float* __restrict__ w_lin, const float* __restrict__ b_lin,
       const float* __restrict__ c1_w, const float* __restrict__ c1_b,
       const float* __restrict__ c2_w, const float* __restrict__ c2_b,
       const float* __restrict__ c3_w, const float* __restrict__ c3_b,
       const float* __restrict__ fc1_w, const float* __restrict__ fc1_b,
       const float* __restrict__ fc2_w, const float* __restrict__ fc2_b,
       float* __restrict__ out)
{
    __shared__ float sbuf[10272];
    __shared__ float sh[NL * NH];
    __shared__ float swl[NO * NH];
    __shared__ float sbl[NO];
    __shared__ int   slen[NL];
    __shared__ float sfc[16];

    float* feat = sbuf;               // [16][50] : 800
    float* w1   = sbuf + 800;         // 2560
    float* y1   = sbuf + 3360;        // 1472
    float* w2   = sbuf + 4832;        // 4096
    float* y2   = sbuf + 8928;        // 704
    float* y3   = sbuf + 9632;        // 608
    float* w3   = sbuf;               // reuse [0,4096) after conv2

    const int b   = blockIdx.x;
    const int tid = threadIdx.x;

    if (tid < NL) slen[tid] = lengths[b * NL + tid];
    for (int i = tid; i < NO * NH; i += 128) swl[i] = w_lin[i];
    if (tid < NO) sbl[tid] = b_lin[tid];
    __syncthreads();
    for (int i = tid; i < NL * NH; i += 128) {
        int l = i / NH, k = i % NH;
        sh[i] = (slen[l] > 0) ? g_hout[(size_t)(b * NL + l) * NH + k] : 0.0f;
    }
    for (int i = tid; i < 2560; i += 128) w1[i] = c1_w[i];
    for (int i = tid; i < 4096; i += 128) w2[i] = c2_w[i];
    __syncthreads();

    for (int i = tid; i < NO * NL; i += 128) {
        int c = i / NL, l = i % NL;
        float s = sbl[c];
        #pragma unroll
        for (int k = 0; k < NH; ++k) s += sh[l * NH + k] * swl[c * NH + k];
        feat[c * NL + l] = (slen[l] > 0) ? fsig(s) : 0.0f;
    }
    __syncthreads();

    // conv1: 16ch k5 s1 -> [32][46]; 4 positions/thread share weight loads
    for (int idx = tid; idx < 32 * 12; idx += 128) {
        int o = idx / 12, pg = idx % 12, pp = pg * 4;
        float a0 = c1_b[o], a1 = a0, a2 = a0, a3 = a0;
        #pragma unroll
        for (int c = 0; c < 16; ++c) {
            const float* f = feat + c * 50 + pp;
            const float* w = w1 + (o * 16 + c) * 5;
            float wv0 = w[0], wv1 = w[1], wv2 = w[2], wv3 = w[3], wv4 = w[4];
            float f0 = f[0], f1 = f[1], f2 = f[2], f3 = f[3];
            float f4 = f[4], f5 = f[5], f6 = f[6], f7 = f[7];
            a0 += f0*wv0 + f1*wv1 + f2*wv2 + f3*wv3 + f4*wv4;
            a1 += f1*wv0 + f2*wv1 + f3*wv2 + f4*wv3 + f5*wv4;
            a2 += f2*wv0 + f3*wv1 + f4*wv2 + f5*wv3 + f6*wv4;
            a3 += f3*wv0 + f4*wv1 + f5*wv2 + f6*wv3 + f7*wv4;
        }
        if (pp + 0 < C1OUT) y1[o * C1OUT + pp + 0] = fmaxf(a0, 0.0f);
        if (pp + 1 < C1OUT) y1[o * C1OUT + pp + 1] = fmaxf(a1, 0.0f);
        if (pp + 2 < C1OUT) y1[o * C1OUT + pp + 2] = fmaxf(a2, 0.0f);
        if (pp + 3 < C1OUT) y1[o * C1OUT + pp + 3] = fmaxf(a3, 0.0f);
    }
    __syncthreads();

    // conv2: 32ch k4 s2 -> [32][22]; 4 positions/thread
    for (int idx = tid; idx < 32 * 6; idx += 128) {
        int o = idx / 6, pg = idx % 6, pp = pg * 4;
        float a0 = c2_b[o], a1 = a0, a2 = a0, a3 = a0;
        #pragma unroll
        for (int c = 0; c < 32; ++c) {
            const float* f = y1 + c * C1OUT + 2 * pp;
            const float* w = w2 + (o * 32 + c) * 4;
            float wv0 = w[0], wv1 = w[1], wv2 = w[2], wv3 = w[3];
            float f0 = f[0], f1 = f[1], f2 = f[2], f3 = f[3], f4 = f[4];
            float f5 = f[5], f6 = f[6], f7 = f[7], f8 = f[8], f9 = f[9];
            a0 += f0*wv0 + f1*wv1 + f2*wv2 + f3*wv3;
            a1 += f2*wv0 + f3*wv1 + f4*wv2 + f5*wv3;
            a2 += f4*wv0 + f5*wv1 + f6*wv2 + f7*wv3;
            a3 += f6*wv0 + f7*wv1 + f8*wv2 + f9*wv3;
        }
        if (pp + 0 < C2OUT) y2[o * C2OUT + pp + 0] = fmaxf(a0, 0.0f);
        if (pp + 1 < C2OUT) y2[o * C2OUT + pp + 1] = fmaxf(a1, 0.0f);
        if (pp + 2 < C2OUT) y2[o * C2OUT + pp + 2] = fmaxf(a2, 0.0f);
        if (pp + 3 < C2OUT) y2[o * C2OUT + pp + 3] = fmaxf(a3, 0.0f);
    }
    __syncthreads();

    for (int i = tid; i < 4096; i += 128) w3[i] = c3_w[i];
    __syncthreads();

    // conv3: 32ch k4 s1 -> [32][19]; 4 positions/thread
    for (int idx = tid; idx < 32 * 5; idx += 128) {
        int o = idx / 5, pg = idx % 5, pp = pg * 4;
        float a0 = c3_b[o], a1 = a0, a2 = a0, a3 = a0;
        #pragma unroll
        for (int c = 0; c < 32; ++c) {
            const float* f = y2 + c * C2OUT + pp;
            const float* w = w3 + (o * 32 + c) * 4;
            float wv0 = w[0], wv1 = w[1], wv2 = w[2], wv3 = w[3];
            float f0 = f[0], f1 = f[1], f2 = f[2], f3 = f[3];
            float f4 = f[4], f5 = f[5], f6 = f[6];
            a0 += f0*wv0 + f1*wv1 + f2*wv2 + f3*wv3;
            a1 += f1*wv0 + f2*wv1 + f3*wv2 + f4*wv3;
            a2 += f2*wv0 + f3*wv1 + f4*wv2 + f5*wv3;
            a3 += f3*wv0 + f4*wv1 + f5*wv2 + f6*wv3;
        }
        if (pp + 0 < C3OUT) y3[o * C3OUT + pp + 0] = fmaxf(a0, 0.0f);
        if (pp + 1 < C3OUT) y3[o * C3OUT + pp + 1] = fmaxf(a1, 0.0f);
        if (pp + 2 < C3OUT) y3[o * C3OUT + pp + 2] = fmaxf(a2, 0.0f);
        if (pp + 3 < C3OUT) y3[o * C3OUT + pp + 3] = fmaxf(a3, 0.0f);
    }
    __syncthreads();

    {
        const int wd = tid >> 5, lane = tid & 31;
        for (int o = wd; o < 16; o += 4) {
            float a = 0.0f;
            const float* w = fc1_w + o * 608;
            for (int k = lane; k < 608; k += 32) a += y3[k] * w[k];
            #pragma unroll
            for (int s = 16; s > 0; s >>= 1) a += __shfl_xor_sync(0xffffffffu, a, s);
            if (lane == 0) sfc[o] = fmaxf(a + fc1_b[o], 0.0f);
        }
    }
    __syncthreads();

    if (tid < 4) {
        float a = fc2_b[tid];
        #pragma unroll
        for (int k = 0; k < 16; ++k) a += sfc[k] * fc2_w[tid * 16 + k];
        out[(size_t)b * 4 + tid] = a;
    }
}

// ---------------- launch ----------------------------------------------------------
extern "C" void kernel_launch(void* const* d_in, const int* in_sizes, int n_in,
                              void* d_out, int out_size)
{
    const float* x       = (const float*)d_in[0];
    const int*   lengths = (const int*)  d_in[1];
    const float* w_ih    = (const float*)d_in[2];
    const float* w_hh    = (const float*)d_in[3];
    const float* b_ih    = (const float*)d_in[4];
    const float* b_hh    = (const float*)d_in[5];
    const float* w_lin   = (const float*)d_in[6];
    const float* b_lin   = (const float*)d_in[7];
    const float* c1_w    = (const float*)d_in[8];
    const float* c1_b    = (const float*)d_in[9];
    const float* c2_w    = (const float*)d_in[10];
    const float* c2_b    = (const float*)d_in[11];
    const float* c3_w    = (const float*)d_in[12];
    const float* c3_b    = (const float*)d_in[13];
    const float* fc1_w   = (const float*)d_in[14];
    const float* fc1_b   = (const float*)d_in[15];
    const float* fc2_w   = (const float*)d_in[16];
    const float* fc2_b   = (const float*)d_in[17];
    float* out = (float*)d_out;

    k_hist<<<(NSEQ + 255) / 256, 256>>>(lengths);
    k_scan<<<1, 64>>>();
    k_scatter<<<(NSEQ + 255) / 256, 256>>>(lengths);

    // LSTM: 4 seqs/thread, unroll 2, snapshot-at-length
    k_lstm<<<NCTA_L, TPB>>>(x, lengths, w_ih, w_hh, b_ih, b_hh);

    k_conv<<<NB, 128>>>(lengths, w_lin, b_lin, c1_w, c1_b, c2_w, c2_b, c3_w, c3_b,
                        fc1_w, fc1_b, fc2_w, fc2_b, out);
}

// round 8
// speedup vs baseline: 1.2556x; 1.0831x over previous
#include <cuda_runtime.h>
#include <cstdint>
#include <math.h>

typedef unsigned long long u64;

#define NB   4096
#define NL   50
#define NT   64
#define NF   3
#define NH   20
#define NG   80
#define NO   16
#define NSEQ (NB*NL)        // 204800
#define TPB  64
#define NQUAD (NSEQ/4)      // 51200
#define NCTA_L (NQUAD/TPB)  // 800

#define L2E 1.4426950408889634f

// ---------------- device scratch (static; zero-initialized at load) -------------
__device__ int   g_hist[64];
__device__ int   g_off[64];
__device__ int   g_order[NSEQ];
__device__ float g_hout[(size_t)NSEQ * NH];

// ---------------- packed f32x2 helpers ------------------------------------------
__device__ __forceinline__ u64 f2pack(float lo, float hi) {
    u64 r; asm("mov.b64 %0, {%1, %2};" : "=l"(r) : "f"(lo), "f"(hi)); return r;
}
__device__ __forceinline__ void f2unpack(u64 v, float& lo, float& hi) {
    asm("mov.b64 {%0, %1}, %2;" : "=f"(lo), "=f"(hi) : "l"(v));
}
__device__ __forceinline__ u64 ffma2(u64 a, u64 b, u64 c) {
    u64 d; asm("fma.rn.f32x2 %0, %1, %2, %3;" : "=l"(d) : "l"(a), "l"(b), "l"(c)); return d;
}
__device__ __forceinline__ u64 add2(u64 a, u64 b) {
    u64 r; asm("add.rn.f32x2 %0, %1, %2;" : "=l"(r) : "l"(a), "l"(b)); return r;
}
__device__ __forceinline__ u64 mul2(u64 a, u64 b) {
    u64 r; asm("mul.rn.f32x2 %0, %1, %2;" : "=l"(r) : "l"(a), "l"(b)); return r;
}
__device__ __forceinline__ float ex2f(float a) {
    float r; asm("ex2.approx.ftz.f32 %0, %1;" : "=f"(r) : "f"(a)); return r;
}
__device__ __forceinline__ float rcpf(float a) {
    float r; asm("rcp.approx.ftz.f32 %0, %1;" : "=f"(r) : "f"(a)); return r;
}

// packed sigmoid from FOLDED preactivation a = -log2e * v  ->  1/(1+2^a)
__device__ __forceinline__ u64 sig2(u64 a, u64 one2) {
    float a0, a1; f2unpack(a, a0, a1);
    u64 e = f2pack(ex2f(a0), ex2f(a1));
    u64 d = add2(e, one2);
    float d0, d1; f2unpack(d, d0, d1);
    return f2pack(rcpf(d0), rcpf(d1));
}
// packed tanh from FOLDED preactivation a = -2*log2e * v  ->  2/(1+2^a) - 1
__device__ __forceinline__ u64 tanh2f(u64 a, u64 one2, u64 two2, u64 m12) {
    u64 r = sig2(a, one2);
    return ffma2(r, two2, m12);
}

// normal-precision activations (conv stage)
__device__ __forceinline__ float fsig(float v) {
    return __fdividef(1.0f, 1.0f + __expf(-v));
}

// ---------------- counting sort, descending length, 3 launches -------------------
__global__ void k_hist(const int* __restrict__ lengths) {
    __shared__ int sh[64];
    if (threadIdx.x < 64) sh[threadIdx.x] = 0;
    __syncthreads();
    int i = blockIdx.x * 256 + threadIdx.x;
    if (i < NSEQ) atomicAdd(&sh[lengths[i] & 63], 1);
    __syncthreads();
    if (threadIdx.x < 64 && sh[threadIdx.x]) atomicAdd(&g_hist[threadIdx.x], sh[threadIdx.x]);
}
__global__ void k_scan() {
    if (threadIdx.x == 0) {
        int acc = 0;
        #pragma unroll
        for (int i = 63; i >= 0; --i) { int v = g_hist[i]; g_off[i] = acc; acc += v; }
    }
    __syncthreads();
    if (threadIdx.x < 64) g_hist[threadIdx.x] = 0;   // deterministic on graph replay
}
__global__ void k_scatter(const int* __restrict__ lengths) {
    __shared__ int sh[64], base[64];
    if (threadIdx.x < 64) sh[threadIdx.x] = 0;
    __syncthreads();
    int i = blockIdx.x * 256 + threadIdx.x, l = 0, r = 0;
    if (i < NSEQ) { l = lengths[i] & 63; r = atomicAdd(&sh[l], 1); }
    __syncthreads();
    if (threadIdx.x < 64) {
        int c = sh[threadIdx.x];
        if (c) base[threadIdx.x] = atomicAdd(&g_off[threadIdx.x], c);
    }
    __syncthreads();
    if (i < NSEQ) g_order[base[l] + r] = i;
}

// ---------------- LSTM: 4 seqs/thread, folded weights, packed activations --------
#define ACC2(accA, accB, wbase) do {                                           \
    const ulonglong2* wp_ = (const ulonglong2*)(wbase);                        \
    ulonglong2 w_;                                                             \
    w_ = wp_[0];                                                               \
    accA = ffma2(hA0,  w_.x, accA); accB = ffma2(hB0,  w_.x, accB);            \
    accA = ffma2(hA1,  w_.y, accA); accB = ffma2(hB1,  w_.y, accB);            \
    w_ = wp_[1];                                                               \
    accA = ffma2(hA2,  w_.x, accA); accB = ffma2(hB2,  w_.x, accB);            \
    accA = ffma2(hA3,  w_.y, accA); accB = ffma2(hB3,  w_.y, accB);            \
    w_ = wp_[2];                                                               \
    accA = ffma2(hA4,  w_.x, accA); accB = ffma2(hB4,  w_.x, accB);            \
    accA = ffma2(hA5,  w_.y, accA); accB = ffma2(hB5,  w_.y, accB);            \
    w_ = wp_[3];                                                               \
    accA = ffma2(hA6,  w_.x, accA); accB = ffma2(hB6,  w_.x, accB);            \
    accA = ffma2(hA7,  w_.y, accA); accB = ffma2(hB7,  w_.y, accB);            \
    w_ = wp_[4];                                                               \
    accA = ffma2(hA8,  w_.x, accA); accB = ffma2(hB8,  w_.x, accB);            \
    accA = ffma2(hA9,  w_.y, accA); accB = ffma2(hB9,  w_.y, accB);            \
    w_ = wp_[5];                                                               \
    accA = ffma2(hA10, w_.x, accA); accB = ffma2(hB10, w_.x, accB);            \
    accA = ffma2(hA11, w_.y, accA); accB = ffma2(hB11, w_.y, accB);            \
    w_ = wp_[6];                                                               \
    accA = ffma2(hA12, w_.x, accA); accB = ffma2(hB12, w_.x, accB);            \
    accA = ffma2(hA13, w_.y, accA); accB = ffma2(hB13, w_.y, accB);            \
    w_ = wp_[7];                                                               \
    accA = ffma2(hA14, w_.x, accA); accB = ffma2(hB14, w_.x, accB);            \
    accA = ffma2(hA15, w_.y, accA); accB = ffma2(hB15, w_.y, accB);            \
    w_ = wp_[8];                                                               \
    accA = ffma2(hA16, w_.x, accA); accB = ffma2(hB16, w_.x, accB);            \
    accA = ffma2(hA17, w_.y, accA); accB = ffma2(hB17, w_.y, accB);            \
    w_ = wp_[9];                                                               \
    accA = ffma2(hA18, w_.x, accA); accB = ffma2(hB18, w_.x, accB);            \
    accA = ffma2(hA19, w_.y, accA); accB = ffma2(hB19, w_.y, accB);            \
} while (0)

#define SNAP(P, SEL, dst) do { float lo_, hi_;                                 \
    f2unpack(P##0,  lo_, hi_); (dst)[0]  = SEL;                                \
    f2unpack(P##1,  lo_, hi_); (dst)[1]  = SEL;                                \
    f2unpack(P##2,  lo_, hi_); (dst)[2]  = SEL;                                \
    f2unpack(P##3,  lo_, hi_); (dst)[3]  = SEL;                                \
    f2unpack(P##4,  lo_, hi_); (dst)[4]  = SEL;                                \
    f2unpack(P##5,  lo_, hi_); (dst)[5]  = SEL;                                \
    f2unpack(P##6,  lo_, hi_); (dst)[6]  = SEL;                                \
    f2unpack(P##7,  lo_, hi_); (dst)[7]  = SEL;                                \
    f2unpack(P##8,  lo_, hi_); (dst)[8]  = SEL;                                \
    f2unpack(P##9,  lo_, hi_); (dst)[9]  = SEL;                                \
    f2unpack(P##10, lo_, hi_); (dst)[10] = SEL;                                \
    f2unpack(P##11, lo_, hi_); (dst)[11] = SEL;                                \
    f2unpack(P##12, lo_, hi_); (dst)[12] = SEL;                                \
    f2unpack(P##13, lo_, hi_); (dst)[13] = SEL;                                \
    f2unpack(P##14, lo_, hi_); (dst)[14] = SEL;                                \
    f2unpack(P##15, lo_, hi_); (dst)[15] = SEL;                                \
    f2unpack(P##16, lo_, hi_); (dst)[16] = SEL;                                \
    f2unpack(P##17, lo_, hi_); (dst)[17] = SEL;                                \
    f2unpack(P##18, lo_, hi_); (dst)[18] = SEL;                                \
    f2unpack(P##19, lo_, hi_); (dst)[19] = SEL;                                \
} while (0)

__global__ void __launch_bounds__(TPB)
k_lstm(const float* __restrict__ x, const int* __restrict__ lengths,
       const float* __restrict__ w_ih, const float* __restrict__ w_hh,
       const float* __restrict__ b_ih, const float* __restrict__ b_hh)
{
    __shared__ __align__(16) u64 sWhh2[NH * 4 * NH];       // 12800 B
    __shared__ __align__(16) u64 sC[NH * 16];              //  2560 B
    __shared__ __align__(16) ulonglong2 cbuf[NH * TPB];    // 20480 B
    __shared__ __align__(16) ulonglong2 hnbuf[NH * TPB];   // 20480 B

    const int tid = threadIdx.x;

    // stage weights with activation-scale FOLDING:
    //   gates i,f,o: * -log2e   (sigma(v) = 1/(1+2^a), a = -log2e*v)
    //   gate  g    : * -2*log2e (tanh(v) = 2/(1+2^a)-1, a = -2log2e*v)
    for (int i = tid; i < NH * 4 * NH; i += TPB) {
        int j = i / 80, g = (i / 20) & 3, k = i % 20;
        float fold = (g == 2) ? (-2.0f * L2E) : (-L2E);
        float w = w_hh[(g * 20 + j) * 20 + k] * fold;
        sWhh2[i] = f2pack(w, w);
    }
    for (int i = tid; i < NH * 16; i += TPB) {
        int j = i >> 4, e = i & 15;
        float w;
        if (e < 4) {
            int r = e * 20 + j;
            float fold = (e == 2) ? (-2.0f * L2E) : (-L2E);
            w = (b_ih[r] + b_hh[r]) * fold;
        } else {
            int g = (e - 4) / 3, k = (e - 4) % 3;
            float fold = (g == 2) ? (-2.0f * L2E) : (-L2E);
            w = w_ih[(g * 20 + j) * 3 + k] * fold;
        }
        sC[i] = f2pack(w, w);
    }
    #pragma unroll
    for (int j = 0; j < NH; ++j) cbuf[j * TPB + tid] = make_ulonglong2(0ull, 0ull);
    __syncthreads();

    const int qid = blockIdx.x * TPB + tid;
    const int s0 = g_order[4 * qid + 0];
    const int s1 = g_order[4 * qid + 1];
    const int s2 = g_order[4 * qid + 2];
    const int s3 = g_order[4 * qid + 3];
    const int len0 = lengths[s0], len1 = lengths[s1];
    const int len2 = lengths[s2], len3 = lengths[s3];
    const int tmax = max(max(len0, len1), max(len2, len3));

    const float* p0 = x + (size_t)s0 * (NT * NF);
    const float* p1 = x + (size_t)s1 * (NT * NF);
    const float* p2 = x + (size_t)s2 * (NT * NF);
    const float* p3 = x + (size_t)s3 * (NT * NF);

    // packed constants
    const u64 ONE2 = f2pack(1.0f, 1.0f);
    const u64 TWO2 = f2pack(2.0f, 2.0f);
    const u64 M12  = f2pack(-1.0f, -1.0f);
    const u64 M2L2 = f2pack(-2.0f * L2E, -2.0f * L2E);

    // h state: 40 named u64 (hn staged in shared)
    u64 hA0 = 0, hA1 = 0, hA2 = 0, hA3 = 0, hA4 = 0, hA5 = 0, hA6 = 0, hA7 = 0,
        hA8 = 0, hA9 = 0, hA10 = 0, hA11 = 0, hA12 = 0, hA13 = 0, hA14 = 0,
        hA15 = 0, hA16 = 0, hA17 = 0, hA18 = 0, hA19 = 0;
    u64 hB0 = 0, hB1 = 0, hB2 = 0, hB3 = 0, hB4 = 0, hB5 = 0, hB6 = 0, hB7 = 0,
        hB8 = 0, hB9 = 0, hB10 = 0, hB11 = 0, hB12 = 0, hB13 = 0, hB14 = 0,
        hB15 = 0, hB16 = 0, hB17 = 0, hB18 = 0, hB19 = 0;

    u64 xA0 = 0, xA1 = 0, xA2 = 0, xB0 = 0, xB1 = 0, xB2 = 0;
    if (tmax > 0) {
        xA0 = f2pack(p0[0], p1[0]); xA1 = f2pack(p0[1], p1[1]); xA2 = f2pack(p0[2], p1[2]);
        xB0 = f2pack(p2[0], p3[0]); xB1 = f2pack(p2[1], p3[1]); xB2 = f2pack(p2[2], p3[2]);
    }

    for (int t = 0; t < tmax; ++t) {
        const int tn = min(t + 1, NT - 1);
        const u64 nA0 = f2pack(p0[3 * tn + 0], p1[3 * tn + 0]);
        const u64 nA1 = f2pack(p0[3 * tn + 1], p1[3 * tn + 1]);
        const u64 nA2 = f2pack(p0[3 * tn + 2], p1[3 * tn + 2]);
        const u64 nB0 = f2pack(p2[3 * tn + 0], p3[3 * tn + 0]);
        const u64 nB1 = f2pack(p2[3 * tn + 1], p3[3 * tn + 1]);
        const u64 nB2 = f2pack(p2[3 * tn + 2], p3[3 * tn + 2]);

        #pragma unroll 2
        for (int j = 0; j < NH; ++j) {
            const ulonglong2* cb_ = (const ulonglong2*)(sC + j * 16);
            const ulonglong2 b01 = cb_[0], b23 = cb_[1];
            const ulonglong2 wa = cb_[2], wb = cb_[3], wc = cb_[4];
            const ulonglong2 wd = cb_[5], we = cb_[6], wf = cb_[7];

            u64 aiA = b01.x, afA = b01.y, agA = b23.x, aoA = b23.y;
            u64 aiB = b01.x, afB = b01.y, agB = b23.x, aoB = b23.y;

            aiA = ffma2(xA0, wa.x, aiA); aiB = ffma2(xB0, wa.x, aiB);
            aiA = ffma2(xA1, wa.y, aiA); aiB = ffma2(xB1, wa.y, aiB);
            aiA = ffma2(xA2, wb.x, aiA); aiB = ffma2(xB2, wb.x, aiB);
            afA = ffma2(xA0, wb.y, afA); afB = ffma2(xB0, wb.y, afB);
            afA = ffma2(xA1, wc.x, afA); afB = ffma2(xB1, wc.x, afB);
            afA = ffma2(xA2, wc.y, afA); afB = ffma2(xB2, wc.y, afB);
            agA = ffma2(xA0, wd.x, agA); agB = ffma2(xB0, wd.x, agB);
            agA = ffma2(xA1, wd.y, agA); agB = ffma2(xB1, wd.y, agB);
            agA = ffma2(xA2, we.x, agA); agB = ffma2(xB2, we.x, agB);
            aoA = ffma2(xA0, we.y, aoA); aoB = ffma2(xB0, we.y, aoB);
            aoA = ffma2(xA1, wf.x, aoA); aoB = ffma2(xB1, wf.x, aoB);
            aoA = ffma2(xA2, wf.y, aoA); aoB = ffma2(xB2, wf.y, aoB);

            ACC2(aiA, aiB, sWhh2 + j * 80);
            ACC2(afA, afB, sWhh2 + j * 80 + 20);
            ACC2(agA, agB, sWhh2 + j * 80 + 40);
            ACC2(aoA, aoB, sWhh2 + j * 80 + 60);

            const ulonglong2 cold = cbuf[j * TPB + tid];
            ulonglong2 cnew, hnew;

            // pack A: packed sigmoid/tanh from folded preactivations
            {
                u64 si = sig2(aiA, ONE2);
                u64 sf = sig2(afA, ONE2);
                u64 tg = tanh2f(agA, ONE2, TWO2, M12);
                u64 so = sig2(aoA, ONE2);
                u64 cn = ffma2(sf, cold.x, mul2(si, tg));
                u64 th = tanh2f(mul2(cn, M2L2), ONE2, TWO2, M12);
                cnew.x = cn;
                hnew.x = mul2(so, th);
            }
            // pack B
            {
                u64 si = sig2(aiB, ONE2);
                u64 sf = sig2(afB, ONE2);
                u64 tg = tanh2f(agB, ONE2, TWO2, M12);
                u64 so = sig2(aoB, ONE2);
                u64 cn = ffma2(sf, cold.y, mul2(si, tg));
                u64 th = tanh2f(mul2(cn, M2L2), ONE2, TWO2, M12);
                cnew.y = cn;
                hnew.y = mul2(so, th);
            }

            cbuf[j * TPB + tid]  = cnew;
            hnbuf[j * TPB + tid] = hnew;
        }

        // commit h from staging into named regs
        #define RELOAD(k) { ulonglong2 v_ = hnbuf[(k) * TPB + tid]; hA##k = v_.x; hB##k = v_.y; }
        RELOAD(0)  RELOAD(1)  RELOAD(2)  RELOAD(3)  RELOAD(4)
        RELOAD(5)  RELOAD(6)  RELOAD(7)  RELOAD(8)  RELOAD(9)
        RELOAD(10) RELOAD(11) RELOAD(12) RELOAD(13) RELOAD(14)
        RELOAD(15) RELOAD(16) RELOAD(17) RELOAD(18) RELOAD(19)
        #undef RELOAD

        const int tp1 = t + 1;
        if (tp1 == len0) { float* d = g_hout + (size_t)s0 * NH; SNAP(hA, lo_, d); }
        if (tp1 == len1) { float* d = g_hout + (size_t)s1 * NH; SNAP(hA, hi_, d); }
        if (tp1 == len2) { float* d = g_hout + (size_t)s2 * NH; SNAP(hB, lo_, d); }
        if (tp1 == len3) { float* d = g_hout + (size_t)s3 * NH; SNAP(hB, hi_, d); }

        xA0 = nA0; xA1 = nA1; xA2 = nA2;
        xB0 = nB0; xB1 = nB1; xB2 = nB2;
    }
}

// ---------------- conv + FC kernel ------------------------------------------------
#define C1OUT 46
#define C2OUT 22
#define C3OUT 19

__global__ void __launch_bounds__(128)
k_conv(const int* __restrict__ lengths,
       const float* __restrict__ w_lin, const float* __restrict__ b_lin,
       const float* __restrict__ c1_w, const float* __restrict__ c1_b,
       const float* __restrict__ c2_w, const float* __restrict__ c2_b,
       const float* __restrict__ c3_w, const float* __restrict__ c3_b,
       const float* __restrict__ fc1_w, const float* __restrict__ fc1_b,
       const float* __restrict__ fc2_w, const float* __restrict__ fc2_b,
       float* __restrict__ out)
{
    __shared__ float sbuf[10272];
    __shared__ float sh[NL * NH];
    __shared__ float swl[NO * NH];
    __shared__ float sbl[NO];
    __shared__ int   slen[NL];
    __shared__ float sfc[16];

    float* feat = sbuf;
    float* w1   = sbuf + 800;
    float* y1   = sbuf + 3360;
    float* w2   = sbuf + 4832;
    float* y2   = sbuf + 8928;
    float* y3   = sbuf + 9632;
    float* w3   = sbuf;   // reuse after conv2

    const int b   = blockIdx.x;
    const int tid = threadIdx.x;

    if (tid < NL) slen[tid] = lengths[b * NL + tid];
    for (int i = tid; i < NO * NH; i += 128) swl[i] = w_lin[i];
    if (tid < NO) sbl[tid] = b_lin[tid];
    __syncthreads();
    for (int i = tid; i < NL * NH; i += 128) {
        int l = i / NH, k = i % NH;
        sh[i] = (slen[l] > 0) ? g_hout[(size_t)(b * NL + l) * NH + k] : 0.0f;
    }
    for (int i = tid; i < 2560; i += 128) w1[i] = c1_w[i];
    for (int i = tid; i < 4096; i += 128) w2[i] = c2_w[i];
    __syncthreads();

    for (int i = tid; i < NO * NL; i += 128) {
        int c = i / NL, l = i % NL;
        float s = sbl[c];
        #pragma unroll
        for (int k = 0; k < NH; ++k) s += sh[l * NH + k] * swl[c * NH + k];
        feat[c * NL + l] = (slen[l] > 0) ? fsig(s) : 0.0f;
    }
    __syncthreads();

    for (int idx = tid; idx < 32 * 12; idx += 128) {
        int o = idx / 12, pg = idx % 12, pp = pg * 4;
        float a0 = c1_b[o], a1 = a0, a2 = a0, a3 = a0;
        #pragma unroll
        for (int c = 0; c < 16; ++c) {
            const float* f = feat + c * 50 + pp;
            const float* w = w1 + (o * 16 + c) * 5;
            float wv0 = w[0], wv1 = w[1], wv2 = w[2], wv3 = w[3], wv4 = w[4];
            float f0 = f[0], f1 = f[1], f2 = f[2], f3 = f[3];
            float f4 = f[4], f5 = f[5], f6 = f[6], f7 = f[7];
            a0 += f0*wv0 + f1*wv1 + f2*wv2 + f3*wv3 + f4*wv4;
            a1 += f1*wv0 + f2*wv1 + f3*wv2 + f4*wv3 + f5*wv4;
            a2 += f2*wv0 + f3*wv1 + f4*wv2 + f5*wv3 + f6*wv4;
            a3 += f3*wv0 + f4*wv1 + f5*wv2 + f6*wv3 + f7*wv4;
        }
        if (pp + 0 < C1OUT) y1[o * C1OUT + pp + 0] = fmaxf(a0, 0.0f);
        if (pp + 1 < C1OUT) y1[o * C1OUT + pp + 1] = fmaxf(a1, 0.0f);
        if (pp + 2 < C1OUT) y1[o * C1OUT + pp + 2] = fmaxf(a2, 0.0f);
        if (pp + 3 < C1OUT) y1[o * C1OUT + pp + 3] = fmaxf(a3, 0.0f);
    }
    __syncthreads();

    for (int idx = tid; idx < 32 * 6; idx += 128) {
        int o = idx / 6, pg = idx % 6, pp = pg * 4;
        float a0 = c2_b[o], a1 = a0, a2 = a0, a3 = a0;
        #pragma unroll
        for (int c = 0; c < 32; ++c) {
            const float* f = y1 + c * C1OUT + 2 * pp;
            const float* w = w2 + (o * 32 + c) * 4;
            float wv0 = w[0], wv1 = w[1], wv2 = w[2], wv3 = w[3];
            float f0 = f[0], f1 = f[1], f2 = f[2], f3 = f[3], f4 = f[4];
            float f5 = f[5], f6 = f[6], f7 = f[7], f8 = f[8], f9 = f[9];
            a0 += f0*wv0 + f1*wv1 + f2*wv2 + f3*wv3;
            a1 += f2*wv0 + f3*wv1 + f4*wv2 + f5*wv3;
            a2 += f4*wv0 + f5*wv1 + f6*wv2 + f7*wv3;
            a3 += f6*wv0 + f7*wv1 + f8*wv2 + f9*wv3;
        }
        if (pp + 0 < C2OUT) y2[o * C2OUT + pp + 0] = fmaxf(a0, 0.0f);
        if (pp + 1 < C2OUT) y2[o * C2OUT + pp + 1] = fmaxf(a1, 0.0f);
        if (pp + 2 < C2OUT) y2[o * C2OUT + pp + 2] = fmaxf(a2, 0.0f);
        if (pp + 3 < C2OUT) y2[o * C2OUT + pp + 3] = fmaxf(a3, 0.0f);
    }
    __syncthreads();

    for (int i = tid; i < 4096; i += 128) w3[i] = c3_w[i];
    __syncthreads();

    for (int idx = tid; idx < 32 * 5; idx += 128) {
        int o = idx / 5, pg = idx % 5, pp = pg * 4;
        float a0 = c3_b[o], a1 = a0, a2 = a0, a3 = a0;
        #pragma unroll
        for (int c = 0; c < 32; ++c) {
            const float* f = y2 + c * C2OUT + pp;
            const float* w = w3 + (o * 32 + c) * 4;
            float wv0 = w[0], wv1 = w[1], wv2 = w[2], wv3 = w[3];
            float f0 = f[0], f1 = f[1], f2 = f[2], f3 = f[3];
            float f4 = f[4], f5 = f[5], f6 = f[6];
            a0 += f0*wv0 + f1*wv1 + f2*wv2 + f3*wv3;
            a1 += f1*wv0 + f2*wv1 + f3*wv2 + f4*wv3;
            a2 += f2*wv0 + f3*wv1 + f4*wv2 + f5*wv3;
            a3 += f3*wv0 + f4*wv1 + f5*wv2 + f6*wv3;
        }
        if (pp + 0 < C3OUT) y3[o * C3OUT + pp + 0] = fmaxf(a0, 0.0f);
        if (pp + 1 < C3OUT) y3[o * C3OUT + pp + 1] = fmaxf(a1, 0.0f);
        if (pp + 2 < C3OUT) y3[o * C3OUT + pp + 2] = fmaxf(a2, 0.0f);
        if (pp + 3 < C3OUT) y3[o * C3OUT + pp + 3] = fmaxf(a3, 0.0f);
    }
    __syncthreads();

    {
        const int wd = tid >> 5, lane = tid & 31;
        for (int o = wd; o < 16; o += 4) {
            float a = 0.0f;
            const float* w = fc1_w + o * 608;
            for (int k = lane; k < 608; k += 32) a += y3[k] * w[k];
            #pragma unroll
            for (int s = 16; s > 0; s >>= 1) a += __shfl_xor_sync(0xffffffffu, a, s);
            if (lane == 0) sfc[o] = fmaxf(a + fc1_b[o], 0.0f);
        }
    }
    __syncthreads();

    if (tid < 4) {
        float a = fc2_b[tid];
        #pragma unroll
        for (int k = 0; k < 16; ++k) a += sfc[k] * fc2_w[tid * 16 + k];
        out[(size_t)b * 4 + tid] = a;
    }
}

// ---------------- launch ----------------------------------------------------------
extern "C" void kernel_launch(void* const* d_in, const int* in_sizes, int n_in,
                              void* d_out, int out_size)
{
    const float* x       = (const float*)d_in[0];
    const int*   lengths = (const int*)  d_in[1];
    const float* w_ih    = (const float*)d_in[2];
    const float* w_hh    = (const float*)d_in[3];
    const float* b_ih    = (const float*)d_in[4];
    const float* b_hh    = (const float*)d_in[5];
    const float* w_lin   = (const float*)d_in[6];
    const float* b_lin   = (const float*)d_in[7];
    const float* c1_w    = (const float*)d_in[8];
    const float* c1_b    = (const float*)d_in[9];
    const float* c2_w    = (const float*)d_in[10];
    const float* c2_b    = (const float*)d_in[11];
    const float* c3_w    = (const float*)d_in[12];
    const float* c3_b    = (const float*)d_in[13];
    const float* fc1_w   = (const float*)d_in[14];
    const float* fc1_b   = (const float*)d_in[15];
    const float* fc2_w   = (const float*)d_in[16];
    const float* fc2_b   = (const float*)d_in[17];
    float* out = (float*)d_out;

    k_hist<<<(NSEQ + 255) / 256, 256>>>(lengths);
    k_scan<<<1, 64>>>();
    k_scatter<<<(NSEQ + 255) / 256, 256>>>(lengths);

    k_lstm<<<NCTA_L, TPB>>>(x, lengths, w_ih, w_hh, b_ih, b_hh);

    k_conv<<<NB, 128>>>(lengths, w_lin, b_lin, c1_w, c1_b, c2_w, c2_b, c3_w, c3_b,
                        fc1_w, fc1_b, fc2_w, fc2_b, out);
}

// round 9
// speedup vs baseline: 1.3256x; 1.0558x over previous
#include <cuda_runtime.h>
#include <cstdint>
#include <math.h>

typedef unsigned long long u64;

#define NB   4096
#define NL   50
#define NT   64
#define NF   3
#define NH   20
#define NG   80
#define NO   16
#define NSEQ (NB*NL)        // 204800
#define TPB  64
#define NQUAD (NSEQ/4)      // 51200
#define NCTA_L (NQUAD/TPB)  // 800

// ---------------- device scratch (static; zero-initialized at load) -------------
__device__ int   g_hist[64];
__device__ int   g_off[64];
__device__ int   g_order[NSEQ];
__device__ float g_hout[(size_t)NSEQ * NH];

// ---------------- packed f32x2 helpers ------------------------------------------
__device__ __forceinline__ u64 f2pack(float lo, float hi) {
    u64 r; asm("mov.b64 %0, {%1, %2};" : "=l"(r) : "f"(lo), "f"(hi)); return r;
}
__device__ __forceinline__ void f2unpack(u64 v, float& lo, float& hi) {
    asm("mov.b64 {%0, %1}, %2;" : "=f"(lo), "=f"(hi) : "l"(v));
}
__device__ __forceinline__ u64 ffma2(u64 a, u64 b, u64 c) {
    u64 d; asm("fma.rn.f32x2 %0, %1, %2, %3;" : "=l"(d) : "l"(a), "l"(b), "l"(c)); return d;
}
__device__ __forceinline__ u64 mul2(u64 a, u64 b) {
    u64 r; asm("mul.rn.f32x2 %0, %1, %2;" : "=l"(r) : "l"(a), "l"(b)); return r;
}
__device__ __forceinline__ float tanhaf(float a) {
    float r; asm("tanh.approx.f32 %0, %1;" : "=f"(r) : "f"(a)); return r;
}
// packed tanh: 2 scalar MUFU.TANH
__device__ __forceinline__ u64 tanh2(u64 a) {
    float a0, a1; f2unpack(a, a0, a1);
    return f2pack(tanhaf(a0), tanhaf(a1));
}

// accurate sigmoid (conv stage only)
__device__ __forceinline__ float fsig(float v) {
    return __fdividef(1.0f, 1.0f + __expf(-v));
}

// ---------------- counting sort, descending length, 3 launches -------------------
__global__ void k_hist(const int* __restrict__ lengths) {
    __shared__ int sh[64];
    if (threadIdx.x < 64) sh[threadIdx.x] = 0;
    __syncthreads();
    int i = blockIdx.x * 256 + threadIdx.x;
    if (i < NSEQ) atomicAdd(&sh[lengths[i] & 63], 1);
    __syncthreads();
    if (threadIdx.x < 64 && sh[threadIdx.x]) atomicAdd(&g_hist[threadIdx.x], sh[threadIdx.x]);
}
__global__ void k_scan() {
    if (threadIdx.x == 0) {
        int acc = 0;
        #pragma unroll
        for (int i = 63; i >= 0; --i) { int v = g_hist[i]; g_off[i] = acc; acc += v; }
    }
    __syncthreads();
    if (threadIdx.x < 64) g_hist[threadIdx.x] = 0;   // deterministic on graph replay
}
__global__ void k_scatter(const int* __restrict__ lengths) {
    __shared__ int sh[64], base[64];
    if (threadIdx.x < 64) sh[threadIdx.x] = 0;
    __syncthreads();
    int i = blockIdx.x * 256 + threadIdx.x, l = 0, r = 0;
    if (i < NSEQ) { l = lengths[i] & 63; r = atomicAdd(&sh[l], 1); }
    __syncthreads();
    if (threadIdx.x < 64) {
        int c = sh[threadIdx.x];
        if (c) base[threadIdx.x] = atomicAdd(&g_off[threadIdx.x], c);
    }
    __syncthreads();
    if (i < NSEQ) g_order[base[l] + r] = i;
}

// ---------------- LSTM: 4 seqs/thread, half-folded weights, MUFU.TANH ------------
#define ACC2(accA, accB, wbase) do {                                           \
    const ulonglong2* wp_ = (const ulonglong2*)(wbase);                        \
    ulonglong2 w_;                                                             \
    w_ = wp_[0];                                                               \
    accA = ffma2(hA0,  w_.x, accA); accB = ffma2(hB0,  w_.x, accB);            \
    accA = ffma2(hA1,  w_.y, accA); accB = ffma2(hB1,  w_.y, accB);            \
    w_ = wp_[1];                                                               \
    accA = ffma2(hA2,  w_.x, accA); accB = ffma2(hB2,  w_.x, accB);            \
    accA = ffma2(hA3,  w_.y, accA); accB = ffma2(hB3,  w_.y, accB);            \
    w_ = wp_[2];                                                               \
    accA = ffma2(hA4,  w_.x, accA); accB = ffma2(hB4,  w_.x, accB);            \
    accA = ffma2(hA5,  w_.y, accA); accB = ffma2(hB5,  w_.y, accB);            \
    w_ = wp_[3];                                                               \
    accA = ffma2(hA6,  w_.x, accA); accB = ffma2(hB6,  w_.x, accB);            \
    accA = ffma2(hA7,  w_.y, accA); accB = ffma2(hB7,  w_.y, accB);            \
    w_ = wp_[4];                                                               \
    accA = ffma2(hA8,  w_.x, accA); accB = ffma2(hB8,  w_.x, accB);            \
    accA = ffma2(hA9,  w_.y, accA); accB = ffma2(hB9,  w_.y, accB);            \
    w_ = wp_[5];                                                               \
    accA = ffma2(hA10, w_.x, accA); accB = ffma2(hB10, w_.x, accB);            \
    accA = ffma2(hA11, w_.y, accA); accB = ffma2(hB11, w_.y, accB);            \
    w_ = wp_[6];                                                               \
    accA = ffma2(hA12, w_.x, accA); accB = ffma2(hB12, w_.x, accB);            \
    accA = ffma2(hA13, w_.y, accA); accB = ffma2(hB13, w_.y, accB);            \
    w_ = wp_[7];                                                               \
    accA = ffma2(hA14, w_.x, accA); accB = ffma2(hB14, w_.x, accB);            \
    accA = ffma2(hA15, w_.y, accA); accB = ffma2(hB15, w_.y, accB);            \
    w_ = wp_[8];                                                               \
    accA = ffma2(hA16, w_.x, accA); accB = ffma2(hB16, w_.x, accB);            \
    accA = ffma2(hA17, w_.y, accA); accB = ffma2(hB17, w_.y, accB);            \
    w_ = wp_[9];                                                               \
    accA = ffma2(hA18, w_.x, accA); accB = ffma2(hB18, w_.x, accB);            \
    accA = ffma2(hA19, w_.y, accA); accB = ffma2(hB19, w_.y, accB);            \
} while (0)

#define SNAP(P, SEL, dst) do { float lo_, hi_;                                 \
    f2unpack(P##0,  lo_, hi_); (dst)[0]  = SEL;                                \
    f2unpack(P##1,  lo_, hi_); (dst)[1]  = SEL;                                \
    f2unpack(P##2,  lo_, hi_); (dst)[2]  = SEL;                                \
    f2unpack(P##3,  lo_, hi_); (dst)[3]  = SEL;                                \
    f2unpack(P##4,  lo_, hi_); (dst)[4]  = SEL;                                \
    f2unpack(P##5,  lo_, hi_); (dst)[5]  = SEL;                                \
    f2unpack(P##6,  lo_, hi_); (dst)[6]  = SEL;                                \
    f2unpack(P##7,  lo_, hi_); (dst)[7]  = SEL;                                \
    f2unpack(P##8,  lo_, hi_); (dst)[8]  = SEL;                                \
    f2unpack(P##9,  lo_, hi_); (dst)[9]  = SEL;                                \
    f2unpack(P##10, lo_, hi_); (dst)[10] = SEL;                                \
    f2unpack(P##11, lo_, hi_); (dst)[11] = SEL;                                \
    f2unpack(P##12, lo_, hi_); (dst)[12] = SEL;                                \
    f2unpack(P##13, lo_, hi_); (dst)[13] = SEL;                                \
    f2unpack(P##14, lo_, hi_); (dst)[14] = SEL;                                \
    f2unpack(P##15, lo_, hi_); (dst)[15] = SEL;                                \
    f2unpack(P##16, lo_, hi_); (dst)[16] = SEL;                                \
    f2unpack(P##17, lo_, hi_); (dst)[17] = SEL;                                \
    f2unpack(P##18, lo_, hi_); (dst)[18] = SEL;                                \
    f2unpack(P##19, lo_, hi_); (dst)[19] = SEL;                                \
} while (0)

__global__ void __launch_bounds__(TPB)
k_lstm(const float* __restrict__ x, const int* __restrict__ lengths,
       const float* __restrict__ w_ih, const float* __restrict__ w_hh,
       const float* __restrict__ b_ih, const float* __restrict__ b_hh)
{
    __shared__ __align__(16) u64 sWhh2[NH * 4 * NH];       // 12800 B
    __shared__ __align__(16) u64 sC[NH * 16];              //  2560 B
    __shared__ __align__(16) ulonglong2 cbuf[NH * TPB];    // 20480 B
    __shared__ __align__(16) ulonglong2 hnbuf[NH * TPB];   // 20480 B

    const int tid = threadIdx.x;

    // weight folding for MUFU.TANH activations:
    //   sigma(v) = 0.5 + 0.5*tanh(0.5 v)  -> fold 0.5 into i,f,o rows
    //   tanh(v)  -> g rows unchanged
    for (int i = tid; i < NH * 4 * NH; i += TPB) {
        int j = i / 80, g = (i / 20) & 3, k = i % 20;
        float fold = (g == 2) ? 1.0f : 0.5f;
        float w = w_hh[(g * 20 + j) * 20 + k] * fold;
        sWhh2[i] = f2pack(w, w);
    }
    for (int i = tid; i < NH * 16; i += TPB) {
        int j = i >> 4, e = i & 15;
        float w;
        if (e < 4) {
            int r = e * 20 + j;
            float fold = (e == 2) ? 1.0f : 0.5f;
            w = (b_ih[r] + b_hh[r]) * fold;
        } else {
            int g = (e - 4) / 3, k = (e - 4) % 3;
            float fold = (g == 2) ? 1.0f : 0.5f;
            w = w_ih[(g * 20 + j) * 3 + k] * fold;
        }
        sC[i] = f2pack(w, w);
    }
    #pragma unroll
    for (int j = 0; j < NH; ++j) cbuf[j * TPB + tid] = make_ulonglong2(0ull, 0ull);
    __syncthreads();

    const int qid = blockIdx.x * TPB + tid;
    const int s0 = g_order[4 * qid + 0];
    const int s1 = g_order[4 * qid + 1];
    const int s2 = g_order[4 * qid + 2];
    const int s3 = g_order[4 * qid + 3];
    const int len0 = lengths[s0], len1 = lengths[s1];
    const int len2 = lengths[s2], len3 = lengths[s3];
    const int tmax = max(max(len0, len1), max(len2, len3));

    const float* p0 = x + (size_t)s0 * (NT * NF);
    const float* p1 = x + (size_t)s1 * (NT * NF);
    const float* p2 = x + (size_t)s2 * (NT * NF);
    const float* p3 = x + (size_t)s3 * (NT * NF);

    const u64 HALF2 = f2pack(0.5f, 0.5f);

    u64 hA0 = 0, hA1 = 0, hA2 = 0, hA3 = 0, hA4 = 0, hA5 = 0, hA6 = 0, hA7 = 0,
        hA8 = 0, hA9 = 0, hA10 = 0, hA11 = 0, hA12 = 0, hA13 = 0, hA14 = 0,
        hA15 = 0, hA16 = 0, hA17 = 0, hA18 = 0, hA19 = 0;
    u64 hB0 = 0, hB1 = 0, hB2 = 0, hB3 = 0, hB4 = 0, hB5 = 0, hB6 = 0, hB7 = 0,
        hB8 = 0, hB9 = 0, hB10 = 0, hB11 = 0, hB12 = 0, hB13 = 0, hB14 = 0,
        hB15 = 0, hB16 = 0, hB17 = 0, hB18 = 0, hB19 = 0;

    u64 xA0 = 0, xA1 = 0, xA2 = 0, xB0 = 0, xB1 = 0, xB2 = 0;
    if (tmax > 0) {
        xA0 = f2pack(p0[0], p1[0]); xA1 = f2pack(p0[1], p1[1]); xA2 = f2pack(p0[2], p1[2]);
        xB0 = f2pack(p2[0], p3[0]); xB1 = f2pack(p2[1], p3[1]); xB2 = f2pack(p2[2], p3[2]);
    }

    for (int t = 0; t < tmax; ++t) {
        const int tn = min(t + 1, NT - 1);
        const u64 nA0 = f2pack(p0[3 * tn + 0], p1[3 * tn + 0]);
        const u64 nA1 = f2pack(p0[3 * tn + 1], p1[3 * tn + 1]);
        const u64 nA2 = f2pack(p0[3 * tn + 2], p1[3 * tn + 2]);
        const u64 nB0 = f2pack(p2[3 * tn + 0], p3[3 * tn + 0]);
        const u64 nB1 = f2pack(p2[3 * tn + 1], p3[3 * tn + 1]);
        const u64 nB2 = f2pack(p2[3 * tn + 2], p3[3 * tn + 2]);

        #pragma unroll 2
        for (int j = 0; j < NH; ++j) {
            const ulonglong2* cb_ = (const ulonglong2*)(sC + j * 16);
            const ulonglong2 b01 = cb_[0], b23 = cb_[1];
            const ulonglong2 wa = cb_[2], wb = cb_[3], wc = cb_[4];
            const ulonglong2 wd = cb_[5], we = cb_[6], wf = cb_[7];

            u64 aiA = b01.x, afA = b01.y, agA = b23.x, aoA = b23.y;
            u64 aiB = b01.x, afB = b01.y, agB = b23.x, aoB = b23.y;

            aiA = ffma2(xA0, wa.x, aiA); aiB = ffma2(xB0, wa.x, aiB);
            aiA = ffma2(xA1, wa.y, aiA); aiB = ffma2(xB1, wa.y, aiB);
            aiA = ffma2(xA2, wb.x, aiA); aiB = ffma2(xB2, wb.x, aiB);
            afA = ffma2(xA0, wb.y, afA); afB = ffma2(xB0, wb.y, afB);
            afA = ffma2(xA1, wc.x, afA); afB = ffma2(xB1, wc.x, afB);
            afA = ffma2(xA2, wc.y, afA); afB = ffma2(xB2, wc.y, afB);
            agA = ffma2(xA0, wd.x, agA); agB = ffma2(xB0, wd.x, agB);
            agA = ffma2(xA1, wd.y, agA); agB = ffma2(xB1, wd.y, agB);
            agA = ffma2(xA2, we.x, agA); agB = ffma2(xB2, we.x, agB);
            aoA = ffma2(xA0, we.y, aoA); aoB = ffma2(xB0, we.y, aoB);
            aoA = ffma2(xA1, wf.x, aoA); aoB = ffma2(xB1, wf.x, aoB);
            aoA = ffma2(xA2, wf.y, aoA); aoB = ffma2(xB2, wf.y, aoB);

            ACC2(aiA, aiB, sWhh2 + j * 80);
            ACC2(afA, afB, sWhh2 + j * 80 + 20);
            ACC2(agA, agB, sWhh2 + j * 80 + 40);
            ACC2(aoA, aoB, sWhh2 + j * 80 + 60);

            const ulonglong2 cold = cbuf[j * TPB + tid];
            ulonglong2 cnew, hnew;

            // pack A: sigma = 0.5 + 0.5*tanh(folded), tanh direct (MUFU.TANH)
            {
                u64 si = ffma2(tanh2(aiA), HALF2, HALF2);
                u64 sf = ffma2(tanh2(afA), HALF2, HALF2);
                u64 tg = tanh2(agA);
                u64 so = ffma2(tanh2(aoA), HALF2, HALF2);
                u64 cn = ffma2(sf, cold.x, mul2(si, tg));
                cnew.x = cn;
                hnew.x = mul2(so, tanh2(cn));
            }
            // pack B
            {
                u64 si = ffma2(tanh2(aiB), HALF2, HALF2);
                u64 sf = ffma2(tanh2(afB), HALF2, HALF2);
                u64 tg = tanh2(agB);
                u64 so = ffma2(tanh2(aoB), HALF2, HALF2);
                u64 cn = ffma2(sf, cold.y, mul2(si, tg));
                cnew.y = cn;
                hnew.y = mul2(so, tanh2(cn));
            }

            cbuf[j * TPB + tid]  = cnew;
            hnbuf[j * TPB + tid] = hnew;
        }

        // commit h from staging into named regs
        #define RELOAD(k) { ulonglong2 v_ = hnbuf[(k) * TPB + tid]; hA##k = v_.x; hB##k = v_.y; }
        RELOAD(0)  RELOAD(1)  RELOAD(2)  RELOAD(3)  RELOAD(4)
        RELOAD(5)  RELOAD(6)  RELOAD(7)  RELOAD(8)  RELOAD(9)
        RELOAD(10) RELOAD(11) RELOAD(12) RELOAD(13) RELOAD(14)
        RELOAD(15) RELOAD(16) RELOAD(17) RELOAD(18) RELOAD(19)
        #undef RELOAD

        const int tp1 = t + 1;
        if (tp1 == len0) { float* d = g_hout + (size_t)s0 * NH; SNAP(hA, lo_, d); }
        if (tp1 == len1) { float* d = g_hout + (size_t)s1 * NH; SNAP(hA, hi_, d); }
        if (tp1 == len2) { float* d = g_hout + (size_t)s2 * NH; SNAP(hB, lo_, d); }
        if (tp1 == len3) { float* d = g_hout + (size_t)s3 * NH; SNAP(hB, hi_, d); }

        xA0 = nA0; xA1 = nA1; xA2 = nA2;
        xB0 = nB0; xB1 = nB1; xB2 = nB2;
    }
}

// ---------------- conv + FC kernel ------------------------------------------------
#define C1OUT 46
#define C2OUT 22
#define C3OUT 19

__global__ void __launch_bounds__(128)
k_conv(const int* __restrict__ lengths,
       const float* __restrict__ w_lin, const float* __restrict__ b_lin,
       const float* __restrict__ c1_w, const float* __restrict__ c1_b,
       const float* __restrict__ c2_w, const float* __restrict__ c2_b,
       const float* __restrict__ c3_w, const float* __restrict__ c3_b,
       const float* __restrict__ fc1_w, const float* __restrict__ fc1_b,
       const float* __restrict__ fc2_w, const float* __restrict__ fc2_b,
       float* __restrict__ out)
{
    __shared__ float sbuf[10272];
    __shared__ float sh[NL * NH];
    __shared__ float swl[NO * NH];
    __shared__ float sbl[NO];
    __shared__ int   slen[NL];
    __shared__ float sfc[16];

    float* feat = sbuf;
    float* w1   = sbuf + 800;
    float* y1   = sbuf + 3360;
    float* w2   = sbuf + 4832;
    float* y2   = sbuf + 8928;
    float* y3   = sbuf + 9632;
    float* w3   = sbuf;   // reuse after conv2

    const int b   = blockIdx.x;
    const int tid = threadIdx.x;

    if (tid < NL) slen[tid] = lengths[b * NL + tid];
    for (int i = tid; i < NO * NH; i += 128) swl[i] = w_lin[i];
    if (tid < NO) sbl[tid] = b_lin[tid];
    __syncthreads();
    for (int i = tid; i < NL * NH; i += 128) {
        int l = i / NH, k = i % NH;
        sh[i] = (slen[l] > 0) ? g_hout[(size_t)(b * NL + l) * NH + k] : 0.0f;
    }
    for (int i = tid; i < 2560; i += 128) w1[i] = c1_w[i];
    for (int i = tid; i < 4096; i += 128) w2[i] = c2_w[i];
    __syncthreads();

    for (int i = tid; i < NO * NL; i += 128) {
        int c = i / NL, l = i % NL;
        float s = sbl[c];
        #pragma unroll
        for (int k = 0; k < NH; ++k) s += sh[l * NH + k] * swl[c * NH + k];
        feat[c * NL + l] = (slen[l] > 0) ? fsig(s) : 0.0f;
    }
    __syncthreads();

    for (int idx = tid; idx < 32 * 12; idx += 128) {
        int o = idx / 12, pg = idx % 12, pp = pg * 4;
        float a0 = c1_b[o], a1 = a0, a2 = a0, a3 = a0;
        #pragma unroll
        for (int c = 0; c < 16; ++c) {
            const float* f = feat + c * 50 + pp;
            const float* w = w1 + (o * 16 + c) * 5;
            float wv0 = w[0], wv1 = w[1], wv2 = w[2], wv3 = w[3], wv4 = w[4];
            float f0 = f[0], f1 = f[1], f2 = f[2], f3 = f[3];
            float f4 = f[4], f5 = f[5], f6 = f[6], f7 = f[7];
            a0 += f0*wv0 + f1*wv1 + f2*wv2 + f3*wv3 + f4*wv4;
            a1 += f1*wv0 + f2*wv1 + f3*wv2 + f4*wv3 + f5*wv4;
            a2 += f2*wv0 + f3*wv1 + f4*wv2 + f5*wv3 + f6*wv4;
            a3 += f3*wv0 + f4*wv1 + f5*wv2 + f6*wv3 + f7*wv4;
        }
        if (pp + 0 < C1OUT) y1[o * C1OUT + pp + 0] = fmaxf(a0, 0.0f);
        if (pp + 1 < C1OUT) y1[o * C1OUT + pp + 1] = fmaxf(a1, 0.0f);
        if (pp + 2 < C1OUT) y1[o * C1OUT + pp + 2] = fmaxf(a2, 0.0f);
        if (pp + 3 < C1OUT) y1[o * C1OUT + pp + 3] = fmaxf(a3, 0.0f);
    }
    __syncthreads();

    for (int idx = tid; idx < 32 * 6; idx += 128) {
        int o = idx / 6, pg = idx % 6, pp = pg * 4;
        float a0 = c2_b[o], a1 = a0, a2 = a0, a3 = a0;
        #pragma unroll
        for (int c = 0; c < 32; ++c) {
            const float* f = y1 + c * C1OUT + 2 * pp;
            const float* w = w2 + (o * 32 + c) * 4;
            float wv0 = w[0], wv1 = w[1], wv2 = w[2], wv3 = w[3];
            float f0 = f[0], f1 = f[1], f2 = f[2], f3 = f[3], f4 = f[4];
            float f5 = f[5], f6 = f[6], f7 = f[7], f8 = f[8], f9 = f[9];
            a0 += f0*wv0 + f1*wv1 + f2*wv2 + f3*wv3;
            a1 += f2*wv0 + f3*wv1 + f4*wv2 + f5*wv3;
            a2 += f4*wv0 + f5*wv1 + f6*wv2 + f7*wv3;
            a3 += f6*wv0 + f7*wv1 + f8*wv2 + f9*wv3;
        }
        if (pp + 0 < C2OUT) y2[o * C2OUT + pp + 0] = fmaxf(a0, 0.0f);
        if (pp + 1 < C2OUT) y2[o * C2OUT + pp + 1] = fmaxf(a1, 0.0f);
        if (pp + 2 < C2OUT) y2[o * C2OUT + pp + 2] = fmaxf(a2, 0.0f);
        if (pp + 3 < C2OUT) y2[o * C2OUT + pp + 3] = fmaxf(a3, 0.0f);
    }
    __syncthreads();

    for (int i = tid; i < 4096; i += 128) w3[i] = c3_w[i];
    __syncthreads();

    for (int idx = tid; idx < 32 * 5; idx += 128) {
        int o = idx / 5, pg = idx % 5, pp = pg * 4;
        float a0 = c3_b[o], a1 = a0, a2 = a0, a3 = a0;
        #pragma unroll
        for (int c = 0; c < 32; ++c) {
            const float* f = y2 + c * C2OUT + pp;
            const float* w = w3 + (o * 32 + c) * 4;
            float wv0 = w[0], wv1 = w[1], wv2 = w[2], wv3 = w[3];
            float f0 = f[0], f1 = f[1], f2 = f[2], f3 = f[3];
            float f4 = f[4], f5 = f[5], f6 = f[6];
            a0 += f0*wv0 + f1*wv1 + f2*wv2 + f3*wv3;
            a1 += f1*wv0 + f2*wv1 + f3*wv2 + f4*wv3;
            a2 += f2*wv0 + f3*wv1 + f4*wv2 + f5*wv3;
            a3 += f3*wv0 + f4*wv1 + f5*wv2 + f6*wv3;
        }
        if (pp + 0 < C3OUT) y3[o * C3OUT + pp + 0] = fmaxf(a0, 0.0f);
        if (pp + 1 < C3OUT) y3[o * C3OUT + pp + 1] = fmaxf(a1, 0.0f);
        if (pp + 2 < C3OUT) y3[o * C3OUT + pp + 2] = fmaxf(a2, 0.0f);
        if (pp + 3 < C3OUT) y3[o * C3OUT + pp + 3] = fmaxf(a3, 0.0f);
    }
    __syncthreads();

    {
        const int wd = tid >> 5, lane = tid & 31;
        for (int o = wd; o < 16; o += 4) {
            float a = 0.0f;
            const float* w = fc1_w + o * 608;
            for (int k = lane; k < 608; k += 32) a += y3[k] * w[k];
            #pragma unroll
            for (int s = 16; s > 0; s >>= 1) a += __shfl_xor_sync(0xffffffffu, a, s);
            if (lane == 0) sfc[o] = fmaxf(a + fc1_b[o], 0.0f);
        }
    }
    __syncthreads();

    if (tid < 4) {
        float a = fc2_b[tid];
        #pragma unroll
        for (int k = 0; k < 16; ++k) a += sfc[k] * fc2_w[tid * 16 + k];
        out[(size_t)b * 4 + tid] = a;
    }
}

// ---------------- launch ----------------------------------------------------------
extern "C" void kernel_launch(void* const* d_in, const int* in_sizes, int n_in,
                              void* d_out, int out_size)
{
    const float* x       = (const float*)d_in[0];
    const int*   lengths = (const int*)  d_in[1];
    const float* w_ih    = (const float*)d_in[2];
    const float* w_hh    = (const float*)d_in[3];
    const float* b_ih    = (const float*)d_in[4];
    const float* b_hh    = (const float*)d_in[5];
    const float* w_lin   = (const float*)d_in[6];
    const float* b_lin   = (const float*)d_in[7];
    const float* c1_w    = (const float*)d_in[8];
    const float* c1_b    = (const float*)d_in[9];
    const float* c2_w    = (const float*)d_in[10];
    const float* c2_b    = (const float*)d_in[11];
    const float* c3_w    = (const float*)d_in[12];
    const float* c3_b    = (const float*)d_in[13];
    const float* fc1_w   = (const float*)d_in[14];
    const float* fc1_b   = (const float*)d_in[15];
    const float* fc2_w   = (const float*)d_in[16];
    const float* fc2_b   = (const float*)d_in[17];
    float* out = (float*)d_out;

    k_hist<<<(NSEQ + 255) / 256, 256>>>(lengths);
    k_scan<<<1, 64>>>();
    k_scatter<<<(NSEQ + 255) / 256, 256>>>(lengths);

    k_lstm<<<NCTA_L, TPB>>>(x, lengths, w_ih, w_hh, b_ih, b_hh);

    k_conv<<<NB, 128>>>(lengths, w_lin, b_lin, c1_w, c1_b, c2_w, c2_b, c3_w, c3_b,
                        fc1_w, fc1_b, fc2_w, fc2_b, out);
}